// round 12
// baseline (speedup 1.0000x reference)
#include <cuda_runtime.h>
#include <cuda_fp16.h>

#define NMAX 50000
#define EMAX 800000
#define HD   96          // hidden/feature dim
#define HD2  48          // half2 per row
#define KC   288         // 3*HD concatenated K dim
#define GMAX 64
#define ALPHA 0.5f
#define SCAN_B 256
#define NBLK_MAX 256     // ceil(NMAX/SCAN_B) = 196 <= 256

// ---------------- static device scratch (no runtime allocation) -------------
__device__ float  d_hA[NMAX * HD];
__device__ float  d_hB[NMAX * HD];
__device__ __half2 d_x16[NMAX * HD2];
__device__ __half2 d_hA16[NMAX * HD2];
__device__ __half2 d_hB16[NMAX * HD2];
__device__ float  d_agg_sd[NMAX * HD];
__device__ float  d_agg_ds[NMAX * HD];
__device__ int    d_deg_dst[NMAX];
__device__ int    d_deg_src[NMAX];
__device__ int    d_cnt_in[NMAX];
__device__ int    d_cnt_out[NMAX];
__device__ int    d_off_in[NMAX + 1];
__device__ int    d_off_out[NMAX + 1];
__device__ int    d_blk_in[NBLK_MAX];
__device__ int    d_blk_out[NBLK_MAX];
__device__ int    d_in_nbr[EMAX];
__device__ int    d_out_nbr[EMAX];
__device__ float  d_inv_dd[NMAX];
__device__ float  d_inv_ds[NMAX];
__device__ float  d_Wcat[3 * KC * HD];
__device__ float  d_bcat[3 * HD];
__device__ float  d_gpool[GMAX * HD];

__device__ __forceinline__ const float* pick_in(const float* x0, int which) {
    return which == 0 ? x0 : (which == 1 ? d_hA : d_hB);
}
__device__ __forceinline__ float* pick_buf(int which) {
    return which == 1 ? d_hA : d_hB;
}
__device__ __forceinline__ const __half2* pick16(int which) {
    return which == 0 ? d_x16 : (which == 1 ? d_hA16 : d_hB16);
}

// ---------------- fused prolog: weights + zeroing + x->fp16 ------------------
__global__ void prep_all(
    const float* __restrict__ x,
    const float* W0s, const float* W0sd, const float* W0ds,
    const float* b0s, const float* b0sd, const float* b0ds,
    const float* W1s, const float* W1sd, const float* W1ds,
    const float* b1s, const float* b1sd, const float* b1ds,
    const float* W2s, const float* W2sd, const float* W2ds,
    const float* b2s, const float* b2sd, const float* b2ds, int n)
{
    int idx = blockIdx.x * blockDim.x + threadIdx.x;
    const float* Wtab[9] = {W0s, W0sd, W0ds, W1s, W1sd, W1ds, W2s, W2sd, W2ds};
    const float* btab[9] = {b0s, b0sd, b0ds, b1s, b1sd, b1ds, b2s, b2sd, b2ds};
    if (idx < 3 * KC * HD) {
        int l   = idx / (KC * HD);
        int rem = idx % (KC * HD);
        int r   = rem / HD, c = rem % HD;
        int region = r / HD, rr = r % HD;
        float scale = (region == 0) ? 1.f : (region == 1 ? (1.f - ALPHA) : ALPHA);
        d_Wcat[idx] = Wtab[l * 3 + region][rr * HD + c] * scale;
    }
    if (idx < 3 * HD) {
        int l = idx / HD, c = idx % HD;
        d_bcat[idx] = btab[l * 3 + 0][c]
                    + (1.f - ALPHA) * btab[l * 3 + 1][c]
                    + ALPHA * btab[l * 3 + 2][c];
    }
    if (idx < n) {
        d_deg_dst[idx] = 0; d_deg_src[idx] = 0;
        d_cnt_in[idx]  = 0; d_cnt_out[idx] = 0;
    }
    if (idx < GMAX * HD) d_gpool[idx] = 0.f;
    if (idx < n * HD2) {
        float2 f = reinterpret_cast<const float2*>(x)[idx];
        d_x16[idx] = __floats2half2_rn(f.x, f.y);
    }
}

// ---------------- fp32 h -> fp16 shadow (coalesced) --------------------------
__global__ void convert_h(int which, int n2) {
    int i = blockIdx.x * blockDim.x + threadIdx.x;
    if (i >= n2) return;
    const float2* src = reinterpret_cast<const float2*>(which == 1 ? d_hA : d_hB);
    __half2* dst = (which == 1) ? d_hA16 : d_hB16;
    float2 f = src[i];
    dst[i] = __floats2half2_rn(f.x, f.y);
}

// ---------------- degree / CSR build ----------------------------------------
__global__ void count_deg(const int* __restrict__ ei, int e) {
    int i = blockIdx.x * blockDim.x + threadIdx.x;
    if (i < e) {
        atomicAdd(&d_deg_src[ei[i]], 1);
        atomicAdd(&d_deg_dst[ei[e + i]], 1);
    }
}

__global__ void deg_block_sums(int n) {
    __shared__ int sa[SCAN_B], sb[SCAN_B];
    int t = threadIdx.x;
    int i = blockIdx.x * SCAN_B + t;
    sa[t] = (i < n) ? d_deg_dst[i] : 0;
    sb[t] = (i < n) ? d_deg_src[i] : 0;
    __syncthreads();
    for (int off = SCAN_B / 2; off > 0; off >>= 1) {
        if (t < off) { sa[t] += sa[t + off]; sb[t] += sb[t + off]; }
        __syncthreads();
    }
    if (t == 0) { d_blk_in[blockIdx.x] = sa[0]; d_blk_out[blockIdx.x] = sb[0]; }
}

__global__ void scan_block_sums(int nb) {
    __shared__ int sa[NBLK_MAX], sb[NBLK_MAX];
    int t = threadIdx.x;
    int va0 = (t < nb) ? d_blk_in[t] : 0;
    int vb0 = (t < nb) ? d_blk_out[t] : 0;
    sa[t] = va0; sb[t] = vb0;
    __syncthreads();
    for (int off = 1; off < NBLK_MAX; off <<= 1) {
        int va = (t >= off) ? sa[t - off] : 0;
        int vb = (t >= off) ? sb[t - off] : 0;
        __syncthreads();
        sa[t] += va; sb[t] += vb;
        __syncthreads();
    }
    if (t < nb) { d_blk_in[t] = sa[t] - va0; d_blk_out[t] = sb[t] - vb0; }
}

__global__ void write_offsets(int n) {
    __shared__ int sa[SCAN_B], sb[SCAN_B];
    int t = threadIdx.x;
    int i = blockIdx.x * SCAN_B + t;
    int da = (i < n) ? d_deg_dst[i] : 0;
    int db = (i < n) ? d_deg_src[i] : 0;
    sa[t] = da; sb[t] = db;
    __syncthreads();
    for (int off = 1; off < SCAN_B; off <<= 1) {
        int va = (t >= off) ? sa[t - off] : 0;
        int vb = (t >= off) ? sb[t - off] : 0;
        __syncthreads();
        sa[t] += va; sb[t] += vb;
        __syncthreads();
    }
    int pa = d_blk_in[blockIdx.x];
    int pb = d_blk_out[blockIdx.x];
    if (i < n) {
        d_off_in[i]  = pa + sa[t] - da;
        d_off_out[i] = pb + sb[t] - db;
        d_inv_dd[i] = 1.f / (float)max(da, 1);
        d_inv_ds[i] = 1.f / (float)max(db, 1);
        if (i == n - 1) {
            d_off_in[n]  = pa + sa[t];
            d_off_out[n] = pb + sb[t];
        }
    }
}

__global__ void fill_csr(const int* __restrict__ ei, int e) {
    int i = blockIdx.x * blockDim.x + threadIdx.x;
    if (i >= e) return;
    int s = ei[i], d = ei[e + i];
    int p = d_off_in[d]  + atomicAdd(&d_cnt_in[d], 1);
    d_in_nbr[p] = s;
    int q = d_off_out[s] + atomicAdd(&d_cnt_out[s], 1);
    d_out_nbr[q] = d;
}

// ---------------- gather: warp per (node, direction), fp16 source ------------
__global__ __launch_bounds__(256)
void gather_agg16(int which_in, int n)
{
    int task = blockIdx.x * 8 + (threadIdx.x >> 5);
    int lane = threadIdx.x & 31;
    int v = task >> 1, dir = task & 1;
    if (v >= n) return;
    const __half2* h = pick16(which_in);

    const int* off = dir ? d_off_out : d_off_in;
    const int* nbr = dir ? d_out_nbr : d_in_nbr;
    float inv = dir ? d_inv_ds[v] : d_inv_dd[v];
    float* o = (dir ? d_agg_ds : d_agg_sd) + (size_t)v * HD;

    bool hi = lane < 16;
    int k = off[v], end = off[v + 1];
    float ax = 0.f, ay = 0.f, bx = 0.f, by = 0.f;
    for (; k + 4 <= end; k += 4) {
        int u0 = __ldg(nbr + k);
        int u1 = __ldg(nbr + k + 1);
        int u2 = __ldg(nbr + k + 2);
        int u3 = __ldg(nbr + k + 3);
        const __half2* r0 = h + (size_t)u0 * HD2;
        const __half2* r1 = h + (size_t)u1 * HD2;
        const __half2* r2 = h + (size_t)u2 * HD2;
        const __half2* r3 = h + (size_t)u3 * HD2;
        float2 f0 = __half22float2(r0[lane]);
        float2 f1 = __half22float2(r1[lane]);
        float2 f2 = __half22float2(r2[lane]);
        float2 f3 = __half22float2(r3[lane]);
        ax += (f0.x + f1.x) + (f2.x + f3.x);
        ay += (f0.y + f1.y) + (f2.y + f3.y);
        if (hi) {
            float2 g0 = __half22float2(r0[32 + lane]);
            float2 g1 = __half22float2(r1[32 + lane]);
            float2 g2 = __half22float2(r2[32 + lane]);
            float2 g3 = __half22float2(r3[32 + lane]);
            bx += (g0.x + g1.x) + (g2.x + g3.x);
            by += (g0.y + g1.y) + (g2.y + g3.y);
        }
    }
    for (; k < end; ++k) {
        int u = __ldg(nbr + k);
        const __half2* r = h + (size_t)u * HD2;
        float2 f = __half22float2(r[lane]);
        ax += f.x; ay += f.y;
        if (hi) {
            float2 g = __half22float2(r[32 + lane]);
            bx += g.x; by += g.y;
        }
    }
    float2* o2 = reinterpret_cast<float2*>(o);
    o2[lane] = make_float2(ax * inv, ay * inv);
    if (hi) o2[32 + lane] = make_float2(bx * inv, by * inv);
}

// ---------------- fused layer GEMM: relu([x|agg_sd|agg_ds] @ Wcat + b) ------
__global__ __launch_bounds__(256)
void gemm_layer(const float* __restrict__ x0, int which_in, int layer,
                int which_out, int n, const int* __restrict__ batch,
                int do_pool)
{
    __shared__ float As[32][132];   // 128 + 4 pad
    __shared__ float Bs[32][96];
    const float* xin = pick_in(x0, which_in);
    const float* Wc = d_Wcat + layer * KC * HD;
    const float* bc = d_bcat + layer * HD;

    int bm  = blockIdx.x * 128;
    int tid = threadIdx.x;
    int tm  = tid & 15;   // 16 groups x 8 rows
    int tn  = tid >> 4;   // 16 groups x 6 cols

    float acc[8][6];
#pragma unroll
    for (int i = 0; i < 8; ++i)
#pragma unroll
        for (int j = 0; j < 6; ++j) acc[i][j] = 0.f;

#pragma unroll 1
    for (int kc = 0; kc < 9; ++kc) {
        const float* src = (kc < 3) ? xin : (kc < 6 ? d_agg_sd : d_agg_ds);
        int kl = (kc % 3) * 32;
#pragma unroll
        for (int t = 0; t < 16; ++t) {
            int i = t * 256 + tid;
            int m = i >> 5, kk = i & 31;
            int gm = bm + m;
            As[kk][m] = (gm < n) ? src[(size_t)gm * HD + kl + kk] : 0.f;
        }
#pragma unroll
        for (int t = 0; t < 12; ++t) {
            int i = t * 256 + tid;
            int kk = i / 96, j = i - kk * 96;
            Bs[kk][j] = Wc[(kc * 32 + kk) * HD + j];
        }
        __syncthreads();
#pragma unroll
        for (int kk = 0; kk < 32; ++kk) {
            float4 a0 = *reinterpret_cast<const float4*>(&As[kk][tm * 8]);
            float4 a1 = *reinterpret_cast<const float4*>(&As[kk][tm * 8 + 4]);
            float2 b0 = *reinterpret_cast<const float2*>(&Bs[kk][tn * 6]);
            float2 b1 = *reinterpret_cast<const float2*>(&Bs[kk][tn * 6 + 2]);
            float2 b2 = *reinterpret_cast<const float2*>(&Bs[kk][tn * 6 + 4]);
            float av[8] = {a0.x, a0.y, a0.z, a0.w, a1.x, a1.y, a1.z, a1.w};
            float bv[6] = {b0.x, b0.y, b1.x, b1.y, b2.x, b2.y};
#pragma unroll
            for (int i = 0; i < 8; ++i)
#pragma unroll
                for (int j = 0; j < 6; ++j) acc[i][j] += av[i] * bv[j];
        }
        __syncthreads();
    }

    if (!do_pool) {
        float* out = pick_buf(which_out);
#pragma unroll
        for (int i = 0; i < 8; ++i) {
            int gm = bm + tm * 8 + i;
            if (gm < n) {
#pragma unroll
                for (int j = 0; j < 6; ++j) {
                    int col = tn * 6 + j;
                    out[(size_t)gm * HD + col] = fmaxf(acc[i][j] + bc[col], 0.f);
                }
            }
        }
    } else {
        // fused ReLU + global max pool (values >= 0 -> int atomicMax valid)
#pragma unroll
        for (int i = 0; i < 8; ++i) {
            int gm = bm + tm * 8 + i;
            if (gm < n) {
                int g = batch[gm];
#pragma unroll
                for (int j = 0; j < 6; ++j) {
                    int col = tn * 6 + j;
                    float v = fmaxf(acc[i][j] + bc[col], 0.f);
                    atomicMax(reinterpret_cast<int*>(&d_gpool[g * HD + col]),
                              __float_as_int(v));
                }
            }
        }
    }
}

// ---------------- final MLP --------------------------------------------------
__global__ void mlp_head(const float* __restrict__ w1, const float* __restrict__ b1,
                         const float* __restrict__ w2, const float* __restrict__ b2,
                         float* __restrict__ out, int g)
{
    int t = blockIdx.x * blockDim.x + threadIdx.x;
    if (t >= g) return;
    float o = b2[0];
#pragma unroll
    for (int j = 0; j < 5; ++j) {
        float s = b1[j];
        for (int k = 0; k < HD; ++k)
            s += d_gpool[t * HD + k] * w1[k * 5 + j];
        o += fmaxf(s, 0.f) * w2[j];
    }
    out[t] = o;
}

// ---------------- launch -----------------------------------------------------
extern "C" void kernel_launch(void* const* d_in, const int* in_sizes, int n_in,
                              void* d_out, int out_size)
{
    const float* x     = (const float*)d_in[0];
    const int*   ei    = (const int*)d_in[1];
    const int*   batch = (const int*)d_in[2];
    int n = in_sizes[0] / HD;
    int e = in_sizes[1] / 2;
    if (n > NMAX) n = NMAX;
    if (e > EMAX) e = EMAX;
    int g = out_size;
    if (g > GMAX) g = GMAX;

    bool sig = (in_sizes[4] == HD);
    auto Wp = [&](int l, int t) -> const float* {
        int base = 3 + l * 6;
        return (const float*)d_in[base + (sig ? t * 2 : t)];
    };
    auto bp = [&](int l, int t) -> const float* {
        int base = 3 + l * 6;
        return (const float*)d_in[base + (sig ? t * 2 + 1 : 3 + t)];
    };
    const float* lin1_w = (const float*)d_in[21];
    const float* lin1_b = (const float*)d_in[22];
    const float* lin2_w = (const float*)d_in[23];
    const float* lin2_b = (const float*)d_in[24];

    int prep_elems = n * HD2;                 // dominates 3*KC*HD
    if (prep_elems < 3 * KC * HD) prep_elems = 3 * KC * HD;
    prep_all<<<(prep_elems + 255) / 256, 256>>>(x,
        Wp(0,0), Wp(0,1), Wp(0,2), bp(0,0), bp(0,1), bp(0,2),
        Wp(1,0), Wp(1,1), Wp(1,2), bp(1,0), bp(1,1), bp(1,2),
        Wp(2,0), Wp(2,1), Wp(2,2), bp(2,0), bp(2,1), bp(2,2), n);

    int nb = (n + SCAN_B - 1) / SCAN_B;
    count_deg<<<(e + 255) / 256, 256>>>(ei, e);
    deg_block_sums<<<nb, SCAN_B>>>(n);
    scan_block_sums<<<1, NBLK_MAX>>>(nb);
    write_offsets<<<nb, SCAN_B>>>(n);
    fill_csr<<<(e + 255) / 256, 256>>>(ei, e);

    const int in_sel[3]  = {0, 1, 2};  // x/x16, hA/hA16, hB/hB16
    const int out_sel[3] = {1, 2, 1};  // hA, hB, (pooled; buffer unused)
    for (int l = 0; l < 3; ++l) {
        gather_agg16<<<(2 * n + 7) / 8, 256>>>(in_sel[l], n);
        gemm_layer<<<(n + 127) / 128, 256>>>(x, in_sel[l], l, out_sel[l], n,
                                             batch, l == 2 ? 1 : 0);
        if (l < 2)
            convert_h<<<(n * HD2 + 255) / 256, 256>>>(out_sel[l], n * HD2);
    }

    mlp_head<<<1, 128>>>(lin1_w, lin1_b, lin2_w, lin2_b, (float*)d_out, g);
}

// round 13
// speedup vs baseline: 1.0374x; 1.0374x over previous
#include <cuda_runtime.h>
#include <cuda_fp16.h>

#define NMAX 50000
#define EMAX 800000
#define HD   96          // hidden/feature dim
#define HD2  48          // half2 per row
#define KC   288         // 3*HD concatenated K dim
#define GMAX 64
#define ALPHA 0.5f
#define SCAN_B 256
#define NBLK_MAX 256     // ceil(NMAX/SCAN_B) = 196 <= 256

// ---------------- static device scratch (no runtime allocation) -------------
__device__ float  d_hA[NMAX * HD];
__device__ float  d_hB[NMAX * HD];
__device__ __half2 d_x16[NMAX * HD2];
__device__ __half2 d_hA16[NMAX * HD2];
__device__ __half2 d_hB16[NMAX * HD2];
__device__ float  d_agg_sd[NMAX * HD];
__device__ float  d_agg_ds[NMAX * HD];
__device__ int    d_deg_dst[NMAX];
__device__ int    d_deg_src[NMAX];
__device__ int    d_cnt_in[NMAX];
__device__ int    d_cnt_out[NMAX];
__device__ int    d_off_in[NMAX + 1];
__device__ int    d_off_out[NMAX + 1];
__device__ int    d_blk_in[NBLK_MAX];
__device__ int    d_blk_out[NBLK_MAX];
__device__ int    d_in_nbr[EMAX];
__device__ int    d_out_nbr[EMAX];
__device__ float  d_inv_dd[NMAX];
__device__ float  d_inv_ds[NMAX];
__device__ float  d_Wcat[3 * KC * HD];
__device__ float  d_bcat[3 * HD];
__device__ float  d_gpool[GMAX * HD];

__device__ __forceinline__ const float* pick_in(const float* x0, int which) {
    return which == 0 ? x0 : (which == 1 ? d_hA : d_hB);
}
__device__ __forceinline__ float* pick_buf(int which) {
    return which == 1 ? d_hA : d_hB;
}
__device__ __forceinline__ const __half2* pick16(int which) {
    return which == 0 ? d_x16 : (which == 1 ? d_hA16 : d_hB16);
}

// ---------------- fused prolog: weights + zeroing + x->fp16 ------------------
__global__ void prep_all(
    const float* __restrict__ x,
    const float* W0s, const float* W0sd, const float* W0ds,
    const float* b0s, const float* b0sd, const float* b0ds,
    const float* W1s, const float* W1sd, const float* W1ds,
    const float* b1s, const float* b1sd, const float* b1ds,
    const float* W2s, const float* W2sd, const float* W2ds,
    const float* b2s, const float* b2sd, const float* b2ds, int n)
{
    int idx = blockIdx.x * blockDim.x + threadIdx.x;
    const float* Wtab[9] = {W0s, W0sd, W0ds, W1s, W1sd, W1ds, W2s, W2sd, W2ds};
    const float* btab[9] = {b0s, b0sd, b0ds, b1s, b1sd, b1ds, b2s, b2sd, b2ds};
    if (idx < 3 * KC * HD) {
        int l   = idx / (KC * HD);
        int rem = idx % (KC * HD);
        int r   = rem / HD, c = rem % HD;
        int region = r / HD, rr = r % HD;
        float scale = (region == 0) ? 1.f : (region == 1 ? (1.f - ALPHA) : ALPHA);
        d_Wcat[idx] = Wtab[l * 3 + region][rr * HD + c] * scale;
    }
    if (idx < 3 * HD) {
        int l = idx / HD, c = idx % HD;
        d_bcat[idx] = btab[l * 3 + 0][c]
                    + (1.f - ALPHA) * btab[l * 3 + 1][c]
                    + ALPHA * btab[l * 3 + 2][c];
    }
    if (idx < n) {
        d_deg_dst[idx] = 0; d_deg_src[idx] = 0;
        d_cnt_in[idx]  = 0; d_cnt_out[idx] = 0;
    }
    if (idx < GMAX * HD) d_gpool[idx] = 0.f;
    if (idx < n * HD2) {
        float2 f = reinterpret_cast<const float2*>(x)[idx];
        d_x16[idx] = __floats2half2_rn(f.x, f.y);
    }
}

// ---------------- fp32 h -> fp16 shadow (coalesced) --------------------------
__global__ void convert_h(int which, int n2) {
    int i = blockIdx.x * blockDim.x + threadIdx.x;
    if (i >= n2) return;
    const float2* src = reinterpret_cast<const float2*>(which == 1 ? d_hA : d_hB);
    __half2* dst = (which == 1) ? d_hA16 : d_hB16;
    float2 f = src[i];
    dst[i] = __floats2half2_rn(f.x, f.y);
}

// ---------------- degree / CSR build ----------------------------------------
__global__ void count_deg(const int* __restrict__ ei, int e) {
    int i = blockIdx.x * blockDim.x + threadIdx.x;
    if (i < e) {
        atomicAdd(&d_deg_src[ei[i]], 1);
        atomicAdd(&d_deg_dst[ei[e + i]], 1);
    }
}

__global__ void deg_block_sums(int n) {
    __shared__ int sa[SCAN_B], sb[SCAN_B];
    int t = threadIdx.x;
    int i = blockIdx.x * SCAN_B + t;
    sa[t] = (i < n) ? d_deg_dst[i] : 0;
    sb[t] = (i < n) ? d_deg_src[i] : 0;
    __syncthreads();
    for (int off = SCAN_B / 2; off > 0; off >>= 1) {
        if (t < off) { sa[t] += sa[t + off]; sb[t] += sb[t + off]; }
        __syncthreads();
    }
    if (t == 0) { d_blk_in[blockIdx.x] = sa[0]; d_blk_out[blockIdx.x] = sb[0]; }
}

__global__ void scan_block_sums(int nb) {
    __shared__ int sa[NBLK_MAX], sb[NBLK_MAX];
    int t = threadIdx.x;
    int va0 = (t < nb) ? d_blk_in[t] : 0;
    int vb0 = (t < nb) ? d_blk_out[t] : 0;
    sa[t] = va0; sb[t] = vb0;
    __syncthreads();
    for (int off = 1; off < NBLK_MAX; off <<= 1) {
        int va = (t >= off) ? sa[t - off] : 0;
        int vb = (t >= off) ? sb[t - off] : 0;
        __syncthreads();
        sa[t] += va; sb[t] += vb;
        __syncthreads();
    }
    if (t < nb) { d_blk_in[t] = sa[t] - va0; d_blk_out[t] = sb[t] - vb0; }
}

__global__ void write_offsets(int n) {
    __shared__ int sa[SCAN_B], sb[SCAN_B];
    int t = threadIdx.x;
    int i = blockIdx.x * SCAN_B + t;
    int da = (i < n) ? d_deg_dst[i] : 0;
    int db = (i < n) ? d_deg_src[i] : 0;
    sa[t] = da; sb[t] = db;
    __syncthreads();
    for (int off = 1; off < SCAN_B; off <<= 1) {
        int va = (t >= off) ? sa[t - off] : 0;
        int vb = (t >= off) ? sb[t - off] : 0;
        __syncthreads();
        sa[t] += va; sb[t] += vb;
        __syncthreads();
    }
    int pa = d_blk_in[blockIdx.x];
    int pb = d_blk_out[blockIdx.x];
    if (i < n) {
        d_off_in[i]  = pa + sa[t] - da;
        d_off_out[i] = pb + sb[t] - db;
        d_inv_dd[i] = 1.f / (float)max(da, 1);
        d_inv_ds[i] = 1.f / (float)max(db, 1);
        if (i == n - 1) {
            d_off_in[n]  = pa + sa[t];
            d_off_out[n] = pb + sb[t];
        }
    }
}

__global__ void fill_csr(const int* __restrict__ ei, int e) {
    int i = blockIdx.x * blockDim.x + threadIdx.x;
    if (i >= e) return;
    int s = ei[i], d = ei[e + i];
    int p = d_off_in[d]  + atomicAdd(&d_cnt_in[d], 1);
    d_in_nbr[p] = s;
    int q = d_off_out[s] + atomicAdd(&d_cnt_out[s], 1);
    d_out_nbr[q] = d;
}

// ---------------- gather: warp per (node, direction), fp16 source ------------
__global__ __launch_bounds__(256)
void gather_agg16(int which_in, int n)
{
    int task = blockIdx.x * 8 + (threadIdx.x >> 5);
    int lane = threadIdx.x & 31;
    int v = task >> 1, dir = task & 1;
    if (v >= n) return;
    const __half2* h = pick16(which_in);

    const int* off = dir ? d_off_out : d_off_in;
    const int* nbr = dir ? d_out_nbr : d_in_nbr;
    float inv = dir ? d_inv_ds[v] : d_inv_dd[v];
    float* o = (dir ? d_agg_ds : d_agg_sd) + (size_t)v * HD;

    bool hi = lane < 16;
    int k = off[v], end = off[v + 1];
    float ax = 0.f, ay = 0.f, bx = 0.f, by = 0.f;
    for (; k + 4 <= end; k += 4) {
        int u0 = __ldg(nbr + k);
        int u1 = __ldg(nbr + k + 1);
        int u2 = __ldg(nbr + k + 2);
        int u3 = __ldg(nbr + k + 3);
        const __half2* r0 = h + (size_t)u0 * HD2;
        const __half2* r1 = h + (size_t)u1 * HD2;
        const __half2* r2 = h + (size_t)u2 * HD2;
        const __half2* r3 = h + (size_t)u3 * HD2;
        float2 f0 = __half22float2(r0[lane]);
        float2 f1 = __half22float2(r1[lane]);
        float2 f2 = __half22float2(r2[lane]);
        float2 f3 = __half22float2(r3[lane]);
        ax += (f0.x + f1.x) + (f2.x + f3.x);
        ay += (f0.y + f1.y) + (f2.y + f3.y);
        if (hi) {
            float2 g0 = __half22float2(r0[32 + lane]);
            float2 g1 = __half22float2(r1[32 + lane]);
            float2 g2 = __half22float2(r2[32 + lane]);
            float2 g3 = __half22float2(r3[32 + lane]);
            bx += (g0.x + g1.x) + (g2.x + g3.x);
            by += (g0.y + g1.y) + (g2.y + g3.y);
        }
    }
    for (; k < end; ++k) {
        int u = __ldg(nbr + k);
        const __half2* r = h + (size_t)u * HD2;
        float2 f = __half22float2(r[lane]);
        ax += f.x; ay += f.y;
        if (hi) {
            float2 g = __half22float2(r[32 + lane]);
            bx += g.x; by += g.y;
        }
    }
    float2* o2 = reinterpret_cast<float2*>(o);
    o2[lane] = make_float2(ax * inv, ay * inv);
    if (hi) o2[32 + lane] = make_float2(bx * inv, by * inv);
}

// ---------------- fused layer GEMM: relu([x|agg_sd|agg_ds] @ Wcat + b) ------
__global__ __launch_bounds__(256)
void gemm_layer(const float* __restrict__ x0, int which_in, int layer,
                int which_out, int n, const int* __restrict__ batch,
                int do_pool)
{
    __shared__ float As[32][132];   // 128 + 4 pad
    __shared__ float Bs[32][96];
    const float* xin = pick_in(x0, which_in);
    const float* Wc = d_Wcat + layer * KC * HD;
    const float* bc = d_bcat + layer * HD;

    int bm  = blockIdx.x * 128;
    int tid = threadIdx.x;
    int tm  = tid & 15;   // 16 groups x 8 rows
    int tn  = tid >> 4;   // 16 groups x 6 cols

    float acc[8][6];
#pragma unroll
    for (int i = 0; i < 8; ++i)
#pragma unroll
        for (int j = 0; j < 6; ++j) acc[i][j] = 0.f;

#pragma unroll 1
    for (int kc = 0; kc < 9; ++kc) {
        const float* src = (kc < 3) ? xin : (kc < 6 ? d_agg_sd : d_agg_ds);
        int kl = (kc % 3) * 32;
#pragma unroll
        for (int t = 0; t < 16; ++t) {
            int i = t * 256 + tid;
            int m = i >> 5, kk = i & 31;
            int gm = bm + m;
            As[kk][m] = (gm < n) ? src[(size_t)gm * HD + kl + kk] : 0.f;
        }
#pragma unroll
        for (int t = 0; t < 12; ++t) {
            int i = t * 256 + tid;
            int kk = i / 96, j = i - kk * 96;
            Bs[kk][j] = Wc[(kc * 32 + kk) * HD + j];
        }
        __syncthreads();
#pragma unroll
        for (int kk = 0; kk < 32; ++kk) {
            float4 a0 = *reinterpret_cast<const float4*>(&As[kk][tm * 8]);
            float4 a1 = *reinterpret_cast<const float4*>(&As[kk][tm * 8 + 4]);
            float2 b0 = *reinterpret_cast<const float2*>(&Bs[kk][tn * 6]);
            float2 b1 = *reinterpret_cast<const float2*>(&Bs[kk][tn * 6 + 2]);
            float2 b2 = *reinterpret_cast<const float2*>(&Bs[kk][tn * 6 + 4]);
            float av[8] = {a0.x, a0.y, a0.z, a0.w, a1.x, a1.y, a1.z, a1.w};
            float bv[6] = {b0.x, b0.y, b1.x, b1.y, b2.x, b2.y};
#pragma unroll
            for (int i = 0; i < 8; ++i)
#pragma unroll
                for (int j = 0; j < 6; ++j) acc[i][j] += av[i] * bv[j];
        }
        __syncthreads();
    }

    if (!do_pool) {
        float* out = pick_buf(which_out);
#pragma unroll
        for (int i = 0; i < 8; ++i) {
            int gm = bm + tm * 8 + i;
            if (gm < n) {
#pragma unroll
                for (int j = 0; j < 6; ++j) {
                    int col = tn * 6 + j;
                    out[(size_t)gm * HD + col] = fmaxf(acc[i][j] + bc[col], 0.f);
                }
            }
        }
    } else {
        // fused ReLU + global max pool (values >= 0 -> int atomicMax valid)
#pragma unroll
        for (int i = 0; i < 8; ++i) {
            int gm = bm + tm * 8 + i;
            if (gm < n) {
                int g = batch[gm];
#pragma unroll
                for (int j = 0; j < 6; ++j) {
                    int col = tn * 6 + j;
                    float v = fmaxf(acc[i][j] + bc[col], 0.f);
                    atomicMax(reinterpret_cast<int*>(&d_gpool[g * HD + col]),
                              __float_as_int(v));
                }
            }
        }
    }
}

// ---------------- final MLP --------------------------------------------------
__global__ void mlp_head(const float* __restrict__ w1, const float* __restrict__ b1,
                         const float* __restrict__ w2, const float* __restrict__ b2,
                         float* __restrict__ out, int g)
{
    int t = blockIdx.x * blockDim.x + threadIdx.x;
    if (t >= g) return;
    float o = b2[0];
#pragma unroll
    for (int j = 0; j < 5; ++j) {
        float s = b1[j];
        for (int k = 0; k < HD; ++k)
            s += d_gpool[t * HD + k] * w1[k * 5 + j];
        o += fmaxf(s, 0.f) * w2[j];
    }
    out[t] = o;
}

// ---------------- launch -----------------------------------------------------
extern "C" void kernel_launch(void* const* d_in, const int* in_sizes, int n_in,
                              void* d_out, int out_size)
{
    const float* x     = (const float*)d_in[0];
    const int*   ei    = (const int*)d_in[1];
    const int*   batch = (const int*)d_in[2];
    int n = in_sizes[0] / HD;
    int e = in_sizes[1] / 2;
    if (n > NMAX) n = NMAX;
    if (e > EMAX) e = EMAX;
    int g = out_size;
    if (g > GMAX) g = GMAX;

    bool sig = (in_sizes[4] == HD);
    auto Wp = [&](int l, int t) -> const float* {
        int base = 3 + l * 6;
        return (const float*)d_in[base + (sig ? t * 2 : t)];
    };
    auto bp = [&](int l, int t) -> const float* {
        int base = 3 + l * 6;
        return (const float*)d_in[base + (sig ? t * 2 + 1 : 3 + t)];
    };
    const float* lin1_w = (const float*)d_in[21];
    const float* lin1_b = (const float*)d_in[22];
    const float* lin2_w = (const float*)d_in[23];
    const float* lin2_b = (const float*)d_in[24];

    int prep_elems = n * HD2;                 // dominates 3*KC*HD
    if (prep_elems < 3 * KC * HD) prep_elems = 3 * KC * HD;
    prep_all<<<(prep_elems + 255) / 256, 256>>>(x,
        Wp(0,0), Wp(0,1), Wp(0,2), bp(0,0), bp(0,1), bp(0,2),
        Wp(1,0), Wp(1,1), Wp(1,2), bp(1,0), bp(1,1), bp(1,2),
        Wp(2,0), Wp(2,1), Wp(2,2), bp(2,0), bp(2,1), bp(2,2), n);

    int nb = (n + SCAN_B - 1) / SCAN_B;
    count_deg<<<(e + 255) / 256, 256>>>(ei, e);
    deg_block_sums<<<nb, SCAN_B>>>(n);
    scan_block_sums<<<1, NBLK_MAX>>>(nb);
    write_offsets<<<nb, SCAN_B>>>(n);
    fill_csr<<<(e + 255) / 256, 256>>>(ei, e);

    const int in_sel[3]  = {0, 1, 2};  // x/x16, hA/hA16, hB/hB16
    const int out_sel[3] = {1, 2, 1};  // hA, hB, (pooled; buffer unused)
    for (int l = 0; l < 3; ++l) {
        gather_agg16<<<(2 * n + 7) / 8, 256>>>(in_sel[l], n);
        gemm_layer<<<(n + 127) / 128, 256>>>(x, in_sel[l], l, out_sel[l], n,
                                             batch, l == 2 ? 1 : 0);
        if (l < 2)
            convert_h<<<(n * HD2 + 255) / 256, 256>>>(out_sel[l], n * HD2);
    }

    mlp_head<<<1, 128>>>(lin1_w, lin1_b, lin2_w, lin2_b, (float*)d_out, g);
}

// round 14
// speedup vs baseline: 1.0411x; 1.0036x over previous
#include <cuda_runtime.h>
#include <cuda_fp16.h>

#define NMAX 50000
#define EMAX 800000
#define HD   96          // hidden/feature dim
#define HD2  48          // half2 per row
#define KC   288         // 3*HD concatenated K dim
#define GMAX 64
#define ALPHA 0.5f
#define SCAN_B 256
#define NBLK_MAX 256     // ceil(NMAX/SCAN_B) = 196 <= 256

// ---------------- static device scratch (no runtime allocation) -------------
__device__ float  d_hA[NMAX * HD];
__device__ float  d_hB[NMAX * HD];
__device__ __half2 d_x16[NMAX * HD2];
__device__ __half2 d_hA16[NMAX * HD2];
__device__ __half2 d_hB16[NMAX * HD2];
__device__ float  d_agg_sd[NMAX * HD];
__device__ float  d_agg_ds[NMAX * HD];
__device__ int    d_deg_dst[NMAX];
__device__ int    d_deg_src[NMAX];
__device__ int    d_cnt_in[NMAX];
__device__ int    d_cnt_out[NMAX];
__device__ int    d_off_in[NMAX + 1];
__device__ int    d_off_out[NMAX + 1];
__device__ int    d_blk_in[NBLK_MAX];
__device__ int    d_blk_out[NBLK_MAX];
__device__ int    d_in_nbr[EMAX];
__device__ int    d_out_nbr[EMAX];
__device__ float  d_inv_dd[NMAX];
__device__ float  d_inv_ds[NMAX];
__device__ float  d_Wcat[3 * KC * HD];
__device__ float  d_bcat[3 * HD];
__device__ float  d_gpool[GMAX * HD];

__device__ __forceinline__ const float* pick_in(const float* x0, int which) {
    return which == 0 ? x0 : (which == 1 ? d_hA : d_hB);
}
__device__ __forceinline__ float* pick_buf(int which) {
    return which == 1 ? d_hA : d_hB;
}
__device__ __forceinline__ const __half2* pick16(int which) {
    return which == 0 ? d_x16 : (which == 1 ? d_hA16 : d_hB16);
}

// ---------------- fused prolog: weights + zeroing + x->fp16 ------------------
__global__ void prep_all(
    const float* __restrict__ x,
    const float* W0s, const float* W0sd, const float* W0ds,
    const float* b0s, const float* b0sd, const float* b0ds,
    const float* W1s, const float* W1sd, const float* W1ds,
    const float* b1s, const float* b1sd, const float* b1ds,
    const float* W2s, const float* W2sd, const float* W2ds,
    const float* b2s, const float* b2sd, const float* b2ds, int n)
{
    int idx = blockIdx.x * blockDim.x + threadIdx.x;
    const float* Wtab[9] = {W0s, W0sd, W0ds, W1s, W1sd, W1ds, W2s, W2sd, W2ds};
    const float* btab[9] = {b0s, b0sd, b0ds, b1s, b1sd, b1ds, b2s, b2sd, b2ds};
    if (idx < 3 * KC * HD) {
        int l   = idx / (KC * HD);
        int rem = idx % (KC * HD);
        int r   = rem / HD, c = rem % HD;
        int region = r / HD, rr = r % HD;
        float scale = (region == 0) ? 1.f : (region == 1 ? (1.f - ALPHA) : ALPHA);
        d_Wcat[idx] = Wtab[l * 3 + region][rr * HD + c] * scale;
    }
    if (idx < 3 * HD) {
        int l = idx / HD, c = idx % HD;
        d_bcat[idx] = btab[l * 3 + 0][c]
                    + (1.f - ALPHA) * btab[l * 3 + 1][c]
                    + ALPHA * btab[l * 3 + 2][c];
    }
    if (idx < n) {
        d_deg_dst[idx] = 0; d_deg_src[idx] = 0;
        d_cnt_in[idx]  = 0; d_cnt_out[idx] = 0;
    }
    if (idx < GMAX * HD) d_gpool[idx] = 0.f;
    if (idx < n * HD2) {
        float2 f = reinterpret_cast<const float2*>(x)[idx];
        d_x16[idx] = __floats2half2_rn(f.x, f.y);
    }
}

// ---------------- fp32 h -> fp16 shadow (coalesced) --------------------------
__global__ void convert_h(int which, int n2) {
    int i = blockIdx.x * blockDim.x + threadIdx.x;
    if (i >= n2) return;
    const float2* src = reinterpret_cast<const float2*>(which == 1 ? d_hA : d_hB);
    __half2* dst = (which == 1) ? d_hA16 : d_hB16;
    float2 f = src[i];
    dst[i] = __floats2half2_rn(f.x, f.y);
}

// ---------------- degree / CSR build ----------------------------------------
__global__ void count_deg(const int* __restrict__ ei, int e) {
    int i = blockIdx.x * blockDim.x + threadIdx.x;
    if (i < e) {
        atomicAdd(&d_deg_src[ei[i]], 1);
        atomicAdd(&d_deg_dst[ei[e + i]], 1);
    }
}

__global__ void deg_block_sums(int n) {
    __shared__ int sa[SCAN_B], sb[SCAN_B];
    int t = threadIdx.x;
    int i = blockIdx.x * SCAN_B + t;
    sa[t] = (i < n) ? d_deg_dst[i] : 0;
    sb[t] = (i < n) ? d_deg_src[i] : 0;
    __syncthreads();
    for (int off = SCAN_B / 2; off > 0; off >>= 1) {
        if (t < off) { sa[t] += sa[t + off]; sb[t] += sb[t + off]; }
        __syncthreads();
    }
    if (t == 0) { d_blk_in[blockIdx.x] = sa[0]; d_blk_out[blockIdx.x] = sb[0]; }
}

__global__ void scan_block_sums(int nb) {
    __shared__ int sa[NBLK_MAX], sb[NBLK_MAX];
    int t = threadIdx.x;
    int va0 = (t < nb) ? d_blk_in[t] : 0;
    int vb0 = (t < nb) ? d_blk_out[t] : 0;
    sa[t] = va0; sb[t] = vb0;
    __syncthreads();
    for (int off = 1; off < NBLK_MAX; off <<= 1) {
        int va = (t >= off) ? sa[t - off] : 0;
        int vb = (t >= off) ? sb[t - off] : 0;
        __syncthreads();
        sa[t] += va; sb[t] += vb;
        __syncthreads();
    }
    if (t < nb) { d_blk_in[t] = sa[t] - va0; d_blk_out[t] = sb[t] - vb0; }
}

__global__ void write_offsets(int n) {
    __shared__ int sa[SCAN_B], sb[SCAN_B];
    int t = threadIdx.x;
    int i = blockIdx.x * SCAN_B + t;
    int da = (i < n) ? d_deg_dst[i] : 0;
    int db = (i < n) ? d_deg_src[i] : 0;
    sa[t] = da; sb[t] = db;
    __syncthreads();
    for (int off = 1; off < SCAN_B; off <<= 1) {
        int va = (t >= off) ? sa[t - off] : 0;
        int vb = (t >= off) ? sb[t - off] : 0;
        __syncthreads();
        sa[t] += va; sb[t] += vb;
        __syncthreads();
    }
    int pa = d_blk_in[blockIdx.x];
    int pb = d_blk_out[blockIdx.x];
    if (i < n) {
        d_off_in[i]  = pa + sa[t] - da;
        d_off_out[i] = pb + sb[t] - db;
        d_inv_dd[i] = 1.f / (float)max(da, 1);
        d_inv_ds[i] = 1.f / (float)max(db, 1);
        if (i == n - 1) {
            d_off_in[n]  = pa + sa[t];
            d_off_out[n] = pb + sb[t];
        }
    }
}

__global__ void fill_csr(const int* __restrict__ ei, int e) {
    int i = blockIdx.x * blockDim.x + threadIdx.x;
    if (i >= e) return;
    int s = ei[i], d = ei[e + i];
    int p = d_off_in[d]  + atomicAdd(&d_cnt_in[d], 1);
    d_in_nbr[p] = s;
    int q = d_off_out[s] + atomicAdd(&d_cnt_out[s], 1);
    d_out_nbr[q] = d;
}

// ---------------- gather: warp per (node, direction), fp16 source ------------
__global__ __launch_bounds__(256)
void gather_agg16(int which_in, int n)
{
    int task = blockIdx.x * 8 + (threadIdx.x >> 5);
    int lane = threadIdx.x & 31;
    int v = task >> 1, dir = task & 1;
    if (v >= n) return;
    const __half2* h = pick16(which_in);

    const int* off = dir ? d_off_out : d_off_in;
    const int* nbr = dir ? d_out_nbr : d_in_nbr;
    float inv = dir ? d_inv_ds[v] : d_inv_dd[v];
    float* o = (dir ? d_agg_ds : d_agg_sd) + (size_t)v * HD;

    bool hi = lane < 16;
    int k = off[v], end = off[v + 1];
    float ax = 0.f, ay = 0.f, bx = 0.f, by = 0.f;
    for (; k + 4 <= end; k += 4) {
        int u0 = __ldg(nbr + k);
        int u1 = __ldg(nbr + k + 1);
        int u2 = __ldg(nbr + k + 2);
        int u3 = __ldg(nbr + k + 3);
        const __half2* r0 = h + (size_t)u0 * HD2;
        const __half2* r1 = h + (size_t)u1 * HD2;
        const __half2* r2 = h + (size_t)u2 * HD2;
        const __half2* r3 = h + (size_t)u3 * HD2;
        float2 f0 = __half22float2(r0[lane]);
        float2 f1 = __half22float2(r1[lane]);
        float2 f2 = __half22float2(r2[lane]);
        float2 f3 = __half22float2(r3[lane]);
        ax += (f0.x + f1.x) + (f2.x + f3.x);
        ay += (f0.y + f1.y) + (f2.y + f3.y);
        if (hi) {
            float2 g0 = __half22float2(r0[32 + lane]);
            float2 g1 = __half22float2(r1[32 + lane]);
            float2 g2 = __half22float2(r2[32 + lane]);
            float2 g3 = __half22float2(r3[32 + lane]);
            bx += (g0.x + g1.x) + (g2.x + g3.x);
            by += (g0.y + g1.y) + (g2.y + g3.y);
        }
    }
    for (; k < end; ++k) {
        int u = __ldg(nbr + k);
        const __half2* r = h + (size_t)u * HD2;
        float2 f = __half22float2(r[lane]);
        ax += f.x; ay += f.y;
        if (hi) {
            float2 g = __half22float2(r[32 + lane]);
            bx += g.x; by += g.y;
        }
    }
    float2* o2 = reinterpret_cast<float2*>(o);
    o2[lane] = make_float2(ax * inv, ay * inv);
    if (hi) o2[32 + lane] = make_float2(bx * inv, by * inv);
}

// ---------------- fused layer GEMM: relu([x|agg_sd|agg_ds] @ Wcat + b) ------
__global__ __launch_bounds__(256)
void gemm_layer(const float* __restrict__ x0, int which_in, int layer,
                int which_out, int n, const int* __restrict__ batch,
                int do_pool)
{
    __shared__ float As[32][132];   // 128 + 4 pad
    __shared__ float Bs[32][96];
    const float* xin = pick_in(x0, which_in);
    const float* Wc = d_Wcat + layer * KC * HD;
    const float* bc = d_bcat + layer * HD;

    int bm  = blockIdx.x * 128;
    int tid = threadIdx.x;
    int tm  = tid & 15;   // 16 groups x 8 rows
    int tn  = tid >> 4;   // 16 groups x 6 cols

    float acc[8][6];
#pragma unroll
    for (int i = 0; i < 8; ++i)
#pragma unroll
        for (int j = 0; j < 6; ++j) acc[i][j] = 0.f;

#pragma unroll 1
    for (int kc = 0; kc < 9; ++kc) {
        const float* src = (kc < 3) ? xin : (kc < 6 ? d_agg_sd : d_agg_ds);
        int kl = (kc % 3) * 32;
#pragma unroll
        for (int t = 0; t < 16; ++t) {
            int i = t * 256 + tid;
            int m = i >> 5, kk = i & 31;
            int gm = bm + m;
            As[kk][m] = (gm < n) ? src[(size_t)gm * HD + kl + kk] : 0.f;
        }
#pragma unroll
        for (int t = 0; t < 12; ++t) {
            int i = t * 256 + tid;
            int kk = i / 96, j = i - kk * 96;
            Bs[kk][j] = Wc[(kc * 32 + kk) * HD + j];
        }
        __syncthreads();
#pragma unroll
        for (int kk = 0; kk < 32; ++kk) {
            float4 a0 = *reinterpret_cast<const float4*>(&As[kk][tm * 8]);
            float4 a1 = *reinterpret_cast<const float4*>(&As[kk][tm * 8 + 4]);
            float2 b0 = *reinterpret_cast<const float2*>(&Bs[kk][tn * 6]);
            float2 b1 = *reinterpret_cast<const float2*>(&Bs[kk][tn * 6 + 2]);
            float2 b2 = *reinterpret_cast<const float2*>(&Bs[kk][tn * 6 + 4]);
            float av[8] = {a0.x, a0.y, a0.z, a0.w, a1.x, a1.y, a1.z, a1.w};
            float bv[6] = {b0.x, b0.y, b1.x, b1.y, b2.x, b2.y};
#pragma unroll
            for (int i = 0; i < 8; ++i)
#pragma unroll
                for (int j = 0; j < 6; ++j) acc[i][j] += av[i] * bv[j];
        }
        __syncthreads();
    }

    if (!do_pool) {
        float* out = pick_buf(which_out);
#pragma unroll
        for (int i = 0; i < 8; ++i) {
            int gm = bm + tm * 8 + i;
            if (gm < n) {
#pragma unroll
                for (int j = 0; j < 6; ++j) {
                    int col = tn * 6 + j;
                    out[(size_t)gm * HD + col] = fmaxf(acc[i][j] + bc[col], 0.f);
                }
            }
        }
    } else {
        // fused ReLU + global max pool (values >= 0 -> int atomicMax valid)
#pragma unroll
        for (int i = 0; i < 8; ++i) {
            int gm = bm + tm * 8 + i;
            if (gm < n) {
                int g = batch[gm];
#pragma unroll
                for (int j = 0; j < 6; ++j) {
                    int col = tn * 6 + j;
                    float v = fmaxf(acc[i][j] + bc[col], 0.f);
                    atomicMax(reinterpret_cast<int*>(&d_gpool[g * HD + col]),
                              __float_as_int(v));
                }
            }
        }
    }
}

// ---------------- final MLP --------------------------------------------------
__global__ void mlp_head(const float* __restrict__ w1, const float* __restrict__ b1,
                         const float* __restrict__ w2, const float* __restrict__ b2,
                         float* __restrict__ out, int g)
{
    int t = blockIdx.x * blockDim.x + threadIdx.x;
    if (t >= g) return;
    float o = b2[0];
#pragma unroll
    for (int j = 0; j < 5; ++j) {
        float s = b1[j];
        for (int k = 0; k < HD; ++k)
            s += d_gpool[t * HD + k] * w1[k * 5 + j];
        o += fmaxf(s, 0.f) * w2[j];
    }
    out[t] = o;
}

// ---------------- launch -----------------------------------------------------
extern "C" void kernel_launch(void* const* d_in, const int* in_sizes, int n_in,
                              void* d_out, int out_size)
{
    const float* x     = (const float*)d_in[0];
    const int*   ei    = (const int*)d_in[1];
    const int*   batch = (const int*)d_in[2];
    int n = in_sizes[0] / HD;
    int e = in_sizes[1] / 2;
    if (n > NMAX) n = NMAX;
    if (e > EMAX) e = EMAX;
    int g = out_size;
    if (g > GMAX) g = GMAX;

    bool sig = (in_sizes[4] == HD);
    auto Wp = [&](int l, int t) -> const float* {
        int base = 3 + l * 6;
        return (const float*)d_in[base + (sig ? t * 2 : t)];
    };
    auto bp = [&](int l, int t) -> const float* {
        int base = 3 + l * 6;
        return (const float*)d_in[base + (sig ? t * 2 + 1 : 3 + t)];
    };
    const float* lin1_w = (const float*)d_in[21];
    const float* lin1_b = (const float*)d_in[22];
    const float* lin2_w = (const float*)d_in[23];
    const float* lin2_b = (const float*)d_in[24];

    int prep_elems = n * HD2;                 // dominates 3*KC*HD
    if (prep_elems < 3 * KC * HD) prep_elems = 3 * KC * HD;
    prep_all<<<(prep_elems + 255) / 256, 256>>>(x,
        Wp(0,0), Wp(0,1), Wp(0,2), bp(0,0), bp(0,1), bp(0,2),
        Wp(1,0), Wp(1,1), Wp(1,2), bp(1,0), bp(1,1), bp(1,2),
        Wp(2,0), Wp(2,1), Wp(2,2), bp(2,0), bp(2,1), bp(2,2), n);

    int nb = (n + SCAN_B - 1) / SCAN_B;
    count_deg<<<(e + 255) / 256, 256>>>(ei, e);
    deg_block_sums<<<nb, SCAN_B>>>(n);
    scan_block_sums<<<1, NBLK_MAX>>>(nb);
    write_offsets<<<nb, SCAN_B>>>(n);
    fill_csr<<<(e + 255) / 256, 256>>>(ei, e);

    const int in_sel[3]  = {0, 1, 2};  // x/x16, hA/hA16, hB/hB16
    const int out_sel[3] = {1, 2, 1};  // hA, hB, (pooled; buffer unused)
    for (int l = 0; l < 3; ++l) {
        gather_agg16<<<(2 * n + 7) / 8, 256>>>(in_sel[l], n);
        gemm_layer<<<(n + 127) / 128, 256>>>(x, in_sel[l], l, out_sel[l], n,
                                             batch, l == 2 ? 1 : 0);
        if (l < 2)
            convert_h<<<(n * HD2 + 255) / 256, 256>>>(out_sel[l], n * HD2);
    }

    mlp_head<<<1, 128>>>(lin1_w, lin1_b, lin2_w, lin2_b, (float*)d_out, g);
}

// round 15
// speedup vs baseline: 2.1425x; 2.0579x over previous
#include <cuda_runtime.h>
#include <cuda_fp16.h>
#include <cstdint>

#define NMAX 50000
#define EMAX 800000
#define HD   96          // hidden/feature dim
#define KC   288         // 3*HD concatenated K dim
#define GMAX 64
#define ALPHA 0.5f
#define SCAN_B 256
#define NBLK_MAX 256     // ceil(NMAX/SCAN_B) = 196 <= 256

// ---------------- static device scratch (no runtime allocation) -------------
__device__ __align__(16) float  d_hA[NMAX * HD];
__device__ __align__(16) float  d_hB[NMAX * HD];
__device__ __align__(16) float  d_agg_sd[NMAX * HD];
__device__ __align__(16) float  d_agg_ds[NMAX * HD];
__device__ int    d_deg_dst[NMAX];
__device__ int    d_deg_src[NMAX];
__device__ int    d_cnt_in[NMAX];
__device__ int    d_cnt_out[NMAX];
__device__ int    d_off_in[NMAX + 1];
__device__ int    d_off_out[NMAX + 1];
__device__ int    d_blk_in[NBLK_MAX];
__device__ int    d_blk_out[NBLK_MAX];
__device__ int    d_in_nbr[EMAX];
__device__ int    d_out_nbr[EMAX];
__device__ float  d_inv_dd[NMAX];
__device__ float  d_inv_ds[NMAX];
__device__ float  d_Wcat[3 * KC * HD];
__device__ __align__(16) __half d_Wcat16[3 * KC * HD];
__device__ float  d_bcat[3 * HD];
__device__ float  d_gpool[GMAX * HD];

__device__ __forceinline__ const float* pick_in(const float* x0, int which) {
    return which == 0 ? x0 : (which == 1 ? d_hA : d_hB);
}
__device__ __forceinline__ float* pick_buf(int which) {
    return which == 1 ? d_hA : d_hB;
}

// ---------------- fused prolog: weights (fp32+fp16) + zeroing ---------------
__global__ void prep_all(
    const float* W0s, const float* W0sd, const float* W0ds,
    const float* b0s, const float* b0sd, const float* b0ds,
    const float* W1s, const float* W1sd, const float* W1ds,
    const float* b1s, const float* b1sd, const float* b1ds,
    const float* W2s, const float* W2sd, const float* W2ds,
    const float* b2s, const float* b2sd, const float* b2ds, int n)
{
    int idx = blockIdx.x * blockDim.x + threadIdx.x;
    const float* Wtab[9] = {W0s, W0sd, W0ds, W1s, W1sd, W1ds, W2s, W2sd, W2ds};
    const float* btab[9] = {b0s, b0sd, b0ds, b1s, b1sd, b1ds, b2s, b2sd, b2ds};
    if (idx < 3 * KC * HD) {
        int l   = idx / (KC * HD);
        int rem = idx % (KC * HD);
        int r   = rem / HD, c = rem % HD;
        int region = r / HD, rr = r % HD;
        float scale = (region == 0) ? 1.f : (region == 1 ? (1.f - ALPHA) : ALPHA);
        float v = Wtab[l * 3 + region][rr * HD + c] * scale;
        d_Wcat[idx]   = v;
        d_Wcat16[idx] = __float2half_rn(v);
    }
    if (idx < 3 * HD) {
        int l = idx / HD, c = idx % HD;
        d_bcat[idx] = btab[l * 3 + 0][c]
                    + (1.f - ALPHA) * btab[l * 3 + 1][c]
                    + ALPHA * btab[l * 3 + 2][c];
    }
    if (idx < n) {
        d_deg_dst[idx] = 0; d_deg_src[idx] = 0;
        d_cnt_in[idx]  = 0; d_cnt_out[idx] = 0;
    }
    if (idx < GMAX * HD) d_gpool[idx] = 0.f;
}

// ---------------- degree / CSR build ----------------------------------------
__global__ void count_deg(const int* __restrict__ ei, int e) {
    int i = blockIdx.x * blockDim.x + threadIdx.x;
    if (i < e) {
        atomicAdd(&d_deg_src[ei[i]], 1);
        atomicAdd(&d_deg_dst[ei[e + i]], 1);
    }
}

__global__ void deg_block_sums(int n) {
    __shared__ int sa[SCAN_B], sb[SCAN_B];
    int t = threadIdx.x;
    int i = blockIdx.x * SCAN_B + t;
    sa[t] = (i < n) ? d_deg_dst[i] : 0;
    sb[t] = (i < n) ? d_deg_src[i] : 0;
    __syncthreads();
    for (int off = SCAN_B / 2; off > 0; off >>= 1) {
        if (t < off) { sa[t] += sa[t + off]; sb[t] += sb[t + off]; }
        __syncthreads();
    }
    if (t == 0) { d_blk_in[blockIdx.x] = sa[0]; d_blk_out[blockIdx.x] = sb[0]; }
}

__global__ void scan_block_sums(int nb) {
    __shared__ int sa[NBLK_MAX], sb[NBLK_MAX];
    int t = threadIdx.x;
    int va0 = (t < nb) ? d_blk_in[t] : 0;
    int vb0 = (t < nb) ? d_blk_out[t] : 0;
    sa[t] = va0; sb[t] = vb0;
    __syncthreads();
    for (int off = 1; off < NBLK_MAX; off <<= 1) {
        int va = (t >= off) ? sa[t - off] : 0;
        int vb = (t >= off) ? sb[t - off] : 0;
        __syncthreads();
        sa[t] += va; sb[t] += vb;
        __syncthreads();
    }
    if (t < nb) { d_blk_in[t] = sa[t] - va0; d_blk_out[t] = sb[t] - vb0; }
}

__global__ void write_offsets(int n) {
    __shared__ int sa[SCAN_B], sb[SCAN_B];
    int t = threadIdx.x;
    int i = blockIdx.x * SCAN_B + t;
    int da = (i < n) ? d_deg_dst[i] : 0;
    int db = (i < n) ? d_deg_src[i] : 0;
    sa[t] = da; sb[t] = db;
    __syncthreads();
    for (int off = 1; off < SCAN_B; off <<= 1) {
        int va = (t >= off) ? sa[t - off] : 0;
        int vb = (t >= off) ? sb[t - off] : 0;
        __syncthreads();
        sa[t] += va; sb[t] += vb;
        __syncthreads();
    }
    int pa = d_blk_in[blockIdx.x];
    int pb = d_blk_out[blockIdx.x];
    if (i < n) {
        d_off_in[i]  = pa + sa[t] - da;
        d_off_out[i] = pb + sb[t] - db;
        d_inv_dd[i] = 1.f / (float)max(da, 1);
        d_inv_ds[i] = 1.f / (float)max(db, 1);
        if (i == n - 1) {
            d_off_in[n]  = pa + sa[t];
            d_off_out[n] = pb + sb[t];
        }
    }
}

__global__ void fill_csr(const int* __restrict__ ei, int e) {
    int i = blockIdx.x * blockDim.x + threadIdx.x;
    if (i >= e) return;
    int s = ei[i], d = ei[e + i];
    int p = d_off_in[d]  + atomicAdd(&d_cnt_in[d], 1);
    d_in_nbr[p] = s;
    int q = d_off_out[s] + atomicAdd(&d_cnt_out[s], 1);
    d_out_nbr[q] = d;
}

// ---------------- gather: warp per (node, direction), ILP-4 (R9 champion) ---
__global__ __launch_bounds__(256)
void gather_agg(const float* __restrict__ x0, int which_in, int n)
{
    int task = blockIdx.x * 8 + (threadIdx.x >> 5);
    int lane = threadIdx.x & 31;
    int v = task >> 1, dir = task & 1;
    if (v >= n) return;
    const float* xin = pick_in(x0, which_in);

    const int* off = dir ? d_off_out : d_off_in;
    const int* nbr = dir ? d_out_nbr : d_in_nbr;
    float inv = dir ? d_inv_ds[v] : d_inv_dd[v];
    float* o = (dir ? d_agg_ds : d_agg_sd) + (size_t)v * HD;

    int k = off[v], end = off[v + 1];
    float a0 = 0.f, a1 = 0.f, a2 = 0.f;
    for (; k + 4 <= end; k += 4) {
        int u0 = __ldg(nbr + k);
        int u1 = __ldg(nbr + k + 1);
        int u2 = __ldg(nbr + k + 2);
        int u3 = __ldg(nbr + k + 3);
        const float* r0 = xin + (size_t)u0 * HD;
        const float* r1 = xin + (size_t)u1 * HD;
        const float* r2 = xin + (size_t)u2 * HD;
        const float* r3 = xin + (size_t)u3 * HD;
        float f00 = r0[lane], f01 = r0[lane + 32], f02 = r0[lane + 64];
        float f10 = r1[lane], f11 = r1[lane + 32], f12 = r1[lane + 64];
        float f20 = r2[lane], f21 = r2[lane + 32], f22 = r2[lane + 64];
        float f30 = r3[lane], f31 = r3[lane + 32], f32 = r3[lane + 64];
        a0 += (f00 + f10) + (f20 + f30);
        a1 += (f01 + f11) + (f21 + f31);
        a2 += (f02 + f12) + (f22 + f32);
    }
    for (; k < end; ++k) {
        int u = __ldg(nbr + k);
        const float* r = xin + (size_t)u * HD;
        a0 += r[lane]; a1 += r[lane + 32]; a2 += r[lane + 64];
    }
    o[lane] = a0 * inv; o[lane + 32] = a1 * inv; o[lane + 64] = a2 * inv;
}

// ---------------- tensor-core helpers ----------------------------------------
__device__ __forceinline__ void ldsm_x4(uint32_t* r, uint32_t addr) {
    asm volatile("ldmatrix.sync.aligned.m8n8.x4.shared.b16 {%0,%1,%2,%3}, [%4];"
                 : "=r"(r[0]), "=r"(r[1]), "=r"(r[2]), "=r"(r[3]) : "r"(addr));
}
__device__ __forceinline__ void ldsm_x2t(uint32_t* r, uint32_t addr) {
    asm volatile("ldmatrix.sync.aligned.m8n8.x2.trans.shared.b16 {%0,%1}, [%2];"
                 : "=r"(r[0]), "=r"(r[1]) : "r"(addr));
}
__device__ __forceinline__ void mma16816(float* d, const uint32_t* a, const uint32_t* b) {
    asm volatile("mma.sync.aligned.m16n8k16.row.col.f32.f16.f16.f32 "
                 "{%0,%1,%2,%3}, {%4,%5,%6,%7}, {%8,%9}, {%0,%1,%2,%3};"
                 : "+f"(d[0]), "+f"(d[1]), "+f"(d[2]), "+f"(d[3])
                 : "r"(a[0]), "r"(a[1]), "r"(a[2]), "r"(a[3]),
                   "r"(b[0]), "r"(b[1]));
}

// ---------------- fused layer GEMM on tensor cores ---------------------------
// out = relu([x|agg_sd|agg_ds] @ Wcat + b), fp16 inputs / fp32 accumulate.
// 128x96 block tile, 8 warps (4 m-groups x 2 n-groups), warp = 32x48.
// A staged [128][40] half (80B stride: conflict-free ldmatrix), B [32][104].
__global__ __launch_bounds__(256)
void gemm_layer_mma(const float* __restrict__ x0, int which_in, int layer,
                    int which_out, int n, const int* __restrict__ batch,
                    int do_pool)
{
    __shared__ __align__(16) __half As[128 * 40];
    __shared__ __align__(16) __half Bs[32 * 104];
    const float* xin = pick_in(x0, which_in);
    const __half* W16 = d_Wcat16 + layer * KC * HD;
    const float* bc = d_bcat + layer * HD;

    int bm   = blockIdx.x * 128;
    int tid  = threadIdx.x;
    int lane = tid & 31;
    int w    = tid >> 5;
    int mg   = (w >> 1) * 32;      // warp m offset within tile
    int ng   = (w & 1) * 48;       // warp n offset within tile

    uint32_t as_base = (uint32_t)__cvta_generic_to_shared(As);
    uint32_t bs_base = (uint32_t)__cvta_generic_to_shared(Bs);

    float acc[2][6][4];
#pragma unroll
    for (int mb = 0; mb < 2; ++mb)
#pragma unroll
        for (int nb = 0; nb < 6; ++nb)
#pragma unroll
            for (int q = 0; q < 4; ++q) acc[mb][nb][q] = 0.f;

    half2* As2 = reinterpret_cast<half2*>(As);
    half2* Bs2 = reinterpret_cast<half2*>(Bs);

#pragma unroll 1
    for (int kc = 0; kc < 9; ++kc) {
        const float* src = (kc < 3) ? xin : (kc < 6 ? d_agg_sd : d_agg_ds);
        const float2* src2 = reinterpret_cast<const float2*>(src);
        int kl2 = (kc % 3) * 16;   // float2 offset within row
        // ---- stage A: 128 rows x 32 k (fp32 -> fp16 in registers) ----
#pragma unroll
        for (int it = 0; it < 8; ++it) {
            int i = it * 256 + tid;
            int m = i >> 4, c = i & 15;
            int gm = bm + m;
            half2 h = __floats2half2_rn(0.f, 0.f);
            if (gm < n) {
                float2 v = src2[(size_t)gm * 48 + kl2 + c];
                h = __floats2half2_rn(v.x, v.y);
            }
            As2[m * 20 + c] = h;
        }
        // ---- stage B: 32 k x 96 n (fp16 weights) ----
        const half2* Wk2 = reinterpret_cast<const half2*>(W16 + kc * 32 * HD);
#pragma unroll
        for (int it = 0; it < 6; ++it) {
            int i = it * 256 + tid;
            int k = i / 48, c = i % 48;
            Bs2[k * 52 + c] = Wk2[k * 48 + c];
        }
        __syncthreads();
        // ---- 2 x k16 MMA steps ----
#pragma unroll
        for (int ks = 0; ks < 32; ks += 16) {
            uint32_t a[2][4], b[6][2];
#pragma unroll
            for (int mb = 0; mb < 2; ++mb) {
                uint32_t addr = as_base +
                    2u * ((mg + mb * 16 + (lane & 15)) * 40 + ks + (lane >> 4) * 8);
                ldsm_x4(a[mb], addr);
            }
#pragma unroll
            for (int nb = 0; nb < 6; ++nb) {
                uint32_t addr = bs_base +
                    2u * ((ks + (lane & 15)) * 104 + ng + nb * 8);
                ldsm_x2t(b[nb], addr);
            }
#pragma unroll
            for (int mb = 0; mb < 2; ++mb)
#pragma unroll
                for (int nb = 0; nb < 6; ++nb)
                    mma16816(acc[mb][nb], a[mb], b[nb]);
        }
        __syncthreads();
    }

    // ---- epilogue: bias + relu (+ fused max-pool on last layer) ----
    int r  = lane >> 2;
    int cp = (lane & 3) * 2;
    if (!do_pool) {
        float* out = pick_buf(which_out);
#pragma unroll
        for (int mb = 0; mb < 2; ++mb) {
            int gm0 = bm + mg + mb * 16 + r;
#pragma unroll
            for (int nb = 0; nb < 6; ++nb) {
                int j = ng + nb * 8 + cp;
                float2 bv = *reinterpret_cast<const float2*>(&bc[j]);
                if (gm0 < n) {
                    float2 o = make_float2(fmaxf(acc[mb][nb][0] + bv.x, 0.f),
                                           fmaxf(acc[mb][nb][1] + bv.y, 0.f));
                    *reinterpret_cast<float2*>(&out[(size_t)gm0 * HD + j]) = o;
                }
                int gm1 = gm0 + 8;
                if (gm1 < n) {
                    float2 o = make_float2(fmaxf(acc[mb][nb][2] + bv.x, 0.f),
                                           fmaxf(acc[mb][nb][3] + bv.y, 0.f));
                    *reinterpret_cast<float2*>(&out[(size_t)gm1 * HD + j]) = o;
                }
            }
        }
    } else {
#pragma unroll
        for (int mb = 0; mb < 2; ++mb) {
            int gm0 = bm + mg + mb * 16 + r;
#pragma unroll
            for (int nb = 0; nb < 6; ++nb) {
                int j = ng + nb * 8 + cp;
                float2 bv = *reinterpret_cast<const float2*>(&bc[j]);
                if (gm0 < n) {
                    int g = batch[gm0];
                    float v0 = fmaxf(acc[mb][nb][0] + bv.x, 0.f);
                    float v1 = fmaxf(acc[mb][nb][1] + bv.y, 0.f);
                    atomicMax((int*)&d_gpool[g * HD + j],     __float_as_int(v0));
                    atomicMax((int*)&d_gpool[g * HD + j + 1], __float_as_int(v1));
                }
                int gm1 = gm0 + 8;
                if (gm1 < n) {
                    int g = batch[gm1];
                    float v2 = fmaxf(acc[mb][nb][2] + bv.x, 0.f);
                    float v3 = fmaxf(acc[mb][nb][3] + bv.y, 0.f);
                    atomicMax((int*)&d_gpool[g * HD + j],     __float_as_int(v2));
                    atomicMax((int*)&d_gpool[g * HD + j + 1], __float_as_int(v3));
                }
            }
        }
    }
}

// ---------------- final MLP --------------------------------------------------
__global__ void mlp_head(const float* __restrict__ w1, const float* __restrict__ b1,
                         const float* __restrict__ w2, const float* __restrict__ b2,
                         float* __restrict__ out, int g)
{
    int t = blockIdx.x * blockDim.x + threadIdx.x;
    if (t >= g) return;
    float o = b2[0];
#pragma unroll
    for (int j = 0; j < 5; ++j) {
        float s = b1[j];
        for (int k = 0; k < HD; ++k)
            s += d_gpool[t * HD + k] * w1[k * 5 + j];
        o += fmaxf(s, 0.f) * w2[j];
    }
    out[t] = o;
}

// ---------------- launch -----------------------------------------------------
extern "C" void kernel_launch(void* const* d_in, const int* in_sizes, int n_in,
                              void* d_out, int out_size)
{
    const float* x     = (const float*)d_in[0];
    const int*   ei    = (const int*)d_in[1];
    const int*   batch = (const int*)d_in[2];
    int n = in_sizes[0] / HD;
    int e = in_sizes[1] / 2;
    if (n > NMAX) n = NMAX;
    if (e > EMAX) e = EMAX;
    int g = out_size;
    if (g > GMAX) g = GMAX;

    bool sig = (in_sizes[4] == HD);
    auto Wp = [&](int l, int t) -> const float* {
        int base = 3 + l * 6;
        return (const float*)d_in[base + (sig ? t * 2 : t)];
    };
    auto bp = [&](int l, int t) -> const float* {
        int base = 3 + l * 6;
        return (const float*)d_in[base + (sig ? t * 2 + 1 : 3 + t)];
    };
    const float* lin1_w = (const float*)d_in[21];
    const float* lin1_b = (const float*)d_in[22];
    const float* lin2_w = (const float*)d_in[23];
    const float* lin2_b = (const float*)d_in[24];

    prep_all<<<(3 * KC * HD + 255) / 256, 256>>>(
        Wp(0,0), Wp(0,1), Wp(0,2), bp(0,0), bp(0,1), bp(0,2),
        Wp(1,0), Wp(1,1), Wp(1,2), bp(1,0), bp(1,1), bp(1,2),
        Wp(2,0), Wp(2,1), Wp(2,2), bp(2,0), bp(2,1), bp(2,2), n);

    int nb = (n + SCAN_B - 1) / SCAN_B;
    count_deg<<<(e + 255) / 256, 256>>>(ei, e);
    deg_block_sums<<<nb, SCAN_B>>>(n);
    scan_block_sums<<<1, NBLK_MAX>>>(nb);
    write_offsets<<<nb, SCAN_B>>>(n);
    fill_csr<<<(e + 255) / 256, 256>>>(ei, e);

    const int in_sel[3]  = {0, 1, 2};  // x, hA, hB
    const int out_sel[3] = {1, 2, 1};  // hA, hB, (pooled; buffer unused)
    for (int l = 0; l < 3; ++l) {
        gather_agg<<<(2 * n + 7) / 8, 256>>>(x, in_sel[l], n);
        gemm_layer_mma<<<(n + 127) / 128, 256>>>(x, in_sel[l], l, out_sel[l], n,
                                                 batch, l == 2 ? 1 : 0);
    }

    mlp_head<<<1, 128>>>(lin1_w, lin1_b, lin2_w, lin2_b, (float*)d_out, g);
}

// round 16
// speedup vs baseline: 2.2188x; 1.0356x over previous
#include <cuda_runtime.h>
#include <cuda_fp16.h>
#include <cstdint>

#define NMAX 50000
#define EMAX 800000
#define HD   96          // hidden/feature dim
#define KC   288         // 3*HD concatenated K dim
#define GMAX 64
#define ALPHA 0.5f
#define SCAN_B 256
#define NBLK_MAX 256     // ceil(NMAX/SCAN_B) = 196 <= 256

// ---------------- static device scratch (no runtime allocation) -------------
__device__ __align__(16) float  d_hA[NMAX * HD];
__device__ __align__(16) float  d_hB[NMAX * HD];
__device__ __align__(16) float  d_agg_sd[NMAX * HD];
__device__ __align__(16) float  d_agg_ds[NMAX * HD];
__device__ int    d_deg_dst[NMAX];
__device__ int    d_deg_src[NMAX];
__device__ int    d_cnt_in[NMAX];
__device__ int    d_cnt_out[NMAX];
__device__ int    d_off_in[NMAX + 1];
__device__ int    d_off_out[NMAX + 1];
__device__ int    d_blk_in[NBLK_MAX];
__device__ int    d_blk_out[NBLK_MAX];
__device__ int    d_in_nbr[EMAX];
__device__ int    d_out_nbr[EMAX];
__device__ float  d_inv_dd[NMAX];
__device__ float  d_inv_ds[NMAX];
__device__ float  d_Wcat[3 * KC * HD];
__device__ __align__(16) __half d_Wcat16[3 * KC * HD];
__device__ float  d_bcat[3 * HD];
__device__ float  d_gpool[GMAX * HD];

__device__ __forceinline__ const float* pick_in(const float* x0, int which) {
    return which == 0 ? x0 : (which == 1 ? d_hA : d_hB);
}
__device__ __forceinline__ float* pick_buf(int which) {
    return which == 1 ? d_hA : d_hB;
}

// ---------------- fused prolog: weights (fp32+fp16) + zeroing ---------------
__global__ void prep_all(
    const float* W0s, const float* W0sd, const float* W0ds,
    const float* b0s, const float* b0sd, const float* b0ds,
    const float* W1s, const float* W1sd, const float* W1ds,
    const float* b1s, const float* b1sd, const float* b1ds,
    const float* W2s, const float* W2sd, const float* W2ds,
    const float* b2s, const float* b2sd, const float* b2ds, int n)
{
    int idx = blockIdx.x * blockDim.x + threadIdx.x;
    const float* Wtab[9] = {W0s, W0sd, W0ds, W1s, W1sd, W1ds, W2s, W2sd, W2ds};
    const float* btab[9] = {b0s, b0sd, b0ds, b1s, b1sd, b1ds, b2s, b2sd, b2ds};
    if (idx < 3 * KC * HD) {
        int l   = idx / (KC * HD);
        int rem = idx % (KC * HD);
        int r   = rem / HD, c = rem % HD;
        int region = r / HD, rr = r % HD;
        float scale = (region == 0) ? 1.f : (region == 1 ? (1.f - ALPHA) : ALPHA);
        float v = Wtab[l * 3 + region][rr * HD + c] * scale;
        d_Wcat[idx]   = v;
        d_Wcat16[idx] = __float2half_rn(v);
    }
    if (idx < 3 * HD) {
        int l = idx / HD, c = idx % HD;
        d_bcat[idx] = btab[l * 3 + 0][c]
                    + (1.f - ALPHA) * btab[l * 3 + 1][c]
                    + ALPHA * btab[l * 3 + 2][c];
    }
    if (idx < n) {
        d_deg_dst[idx] = 0; d_deg_src[idx] = 0;
        d_cnt_in[idx]  = 0; d_cnt_out[idx] = 0;
    }
    if (idx < GMAX * HD) d_gpool[idx] = 0.f;
}

// ---------------- degree / CSR build ----------------------------------------
__global__ void count_deg(const int* __restrict__ ei, int e) {
    int i = blockIdx.x * blockDim.x + threadIdx.x;
    if (i < e) {
        atomicAdd(&d_deg_src[ei[i]], 1);
        atomicAdd(&d_deg_dst[ei[e + i]], 1);
    }
}

__global__ void deg_block_sums(int n) {
    __shared__ int sa[SCAN_B], sb[SCAN_B];
    int t = threadIdx.x;
    int i = blockIdx.x * SCAN_B + t;
    sa[t] = (i < n) ? d_deg_dst[i] : 0;
    sb[t] = (i < n) ? d_deg_src[i] : 0;
    __syncthreads();
    for (int off = SCAN_B / 2; off > 0; off >>= 1) {
        if (t < off) { sa[t] += sa[t + off]; sb[t] += sb[t + off]; }
        __syncthreads();
    }
    if (t == 0) { d_blk_in[blockIdx.x] = sa[0]; d_blk_out[blockIdx.x] = sb[0]; }
}

__global__ void scan_block_sums(int nb) {
    __shared__ int sa[NBLK_MAX], sb[NBLK_MAX];
    int t = threadIdx.x;
    int va0 = (t < nb) ? d_blk_in[t] : 0;
    int vb0 = (t < nb) ? d_blk_out[t] : 0;
    sa[t] = va0; sb[t] = vb0;
    __syncthreads();
    for (int off = 1; off < NBLK_MAX; off <<= 1) {
        int va = (t >= off) ? sa[t - off] : 0;
        int vb = (t >= off) ? sb[t - off] : 0;
        __syncthreads();
        sa[t] += va; sb[t] += vb;
        __syncthreads();
    }
    if (t < nb) { d_blk_in[t] = sa[t] - va0; d_blk_out[t] = sb[t] - vb0; }
}

__global__ void write_offsets(int n) {
    __shared__ int sa[SCAN_B], sb[SCAN_B];
    int t = threadIdx.x;
    int i = blockIdx.x * SCAN_B + t;
    int da = (i < n) ? d_deg_dst[i] : 0;
    int db = (i < n) ? d_deg_src[i] : 0;
    sa[t] = da; sb[t] = db;
    __syncthreads();
    for (int off = 1; off < SCAN_B; off <<= 1) {
        int va = (t >= off) ? sa[t - off] : 0;
        int vb = (t >= off) ? sb[t - off] : 0;
        __syncthreads();
        sa[t] += va; sb[t] += vb;
        __syncthreads();
    }
    int pa = d_blk_in[blockIdx.x];
    int pb = d_blk_out[blockIdx.x];
    if (i < n) {
        d_off_in[i]  = pa + sa[t] - da;
        d_off_out[i] = pb + sb[t] - db;
        d_inv_dd[i] = 1.f / (float)max(da, 1);
        d_inv_ds[i] = 1.f / (float)max(db, 1);
        if (i == n - 1) {
            d_off_in[n]  = pa + sa[t];
            d_off_out[n] = pb + sb[t];
        }
    }
}

__global__ void fill_csr(const int* __restrict__ ei, int e) {
    int i = blockIdx.x * blockDim.x + threadIdx.x;
    if (i >= e) return;
    int s = ei[i], d = ei[e + i];
    int p = d_off_in[d]  + atomicAdd(&d_cnt_in[d], 1);
    d_in_nbr[p] = s;
    int q = d_off_out[s] + atomicAdd(&d_cnt_out[s], 1);
    d_out_nbr[q] = d;
}

// ---------------- gather: warp per (node, direction), ILP-4 (R9 champion) ---
__global__ __launch_bounds__(256)
void gather_agg(const float* __restrict__ x0, int which_in, int n)
{
    int task = blockIdx.x * 8 + (threadIdx.x >> 5);
    int lane = threadIdx.x & 31;
    int v = task >> 1, dir = task & 1;
    if (v >= n) return;
    const float* xin = pick_in(x0, which_in);

    const int* off = dir ? d_off_out : d_off_in;
    const int* nbr = dir ? d_out_nbr : d_in_nbr;
    float inv = dir ? d_inv_ds[v] : d_inv_dd[v];
    float* o = (dir ? d_agg_ds : d_agg_sd) + (size_t)v * HD;

    int k = off[v], end = off[v + 1];
    float a0 = 0.f, a1 = 0.f, a2 = 0.f;
    for (; k + 4 <= end; k += 4) {
        int u0 = __ldg(nbr + k);
        int u1 = __ldg(nbr + k + 1);
        int u2 = __ldg(nbr + k + 2);
        int u3 = __ldg(nbr + k + 3);
        const float* r0 = xin + (size_t)u0 * HD;
        const float* r1 = xin + (size_t)u1 * HD;
        const float* r2 = xin + (size_t)u2 * HD;
        const float* r3 = xin + (size_t)u3 * HD;
        float f00 = r0[lane], f01 = r0[lane + 32], f02 = r0[lane + 64];
        float f10 = r1[lane], f11 = r1[lane + 32], f12 = r1[lane + 64];
        float f20 = r2[lane], f21 = r2[lane + 32], f22 = r2[lane + 64];
        float f30 = r3[lane], f31 = r3[lane + 32], f32 = r3[lane + 64];
        a0 += (f00 + f10) + (f20 + f30);
        a1 += (f01 + f11) + (f21 + f31);
        a2 += (f02 + f12) + (f22 + f32);
    }
    for (; k < end; ++k) {
        int u = __ldg(nbr + k);
        const float* r = xin + (size_t)u * HD;
        a0 += r[lane]; a1 += r[lane + 32]; a2 += r[lane + 64];
    }
    o[lane] = a0 * inv; o[lane + 32] = a1 * inv; o[lane + 64] = a2 * inv;
}

// ---------------- tensor-core helpers ----------------------------------------
__device__ __forceinline__ void ldsm_x4(uint32_t* r, uint32_t addr) {
    asm volatile("ldmatrix.sync.aligned.m8n8.x4.shared.b16 {%0,%1,%2,%3}, [%4];"
                 : "=r"(r[0]), "=r"(r[1]), "=r"(r[2]), "=r"(r[3]) : "r"(addr));
}
__device__ __forceinline__ void ldsm_x2t(uint32_t* r, uint32_t addr) {
    asm volatile("ldmatrix.sync.aligned.m8n8.x2.trans.shared.b16 {%0,%1}, [%2];"
                 : "=r"(r[0]), "=r"(r[1]) : "r"(addr));
}
__device__ __forceinline__ void mma16816(float* d, const uint32_t* a, const uint32_t* b) {
    asm volatile("mma.sync.aligned.m16n8k16.row.col.f32.f16.f16.f32 "
                 "{%0,%1,%2,%3}, {%4,%5,%6,%7}, {%8,%9}, {%0,%1,%2,%3};"
                 : "+f"(d[0]), "+f"(d[1]), "+f"(d[2]), "+f"(d[3])
                 : "r"(a[0]), "r"(a[1]), "r"(a[2]), "r"(a[3]),
                   "r"(b[0]), "r"(b[1]));
}

// ---------------- fused layer GEMM on tensor cores ---------------------------
// out = relu([x|agg_sd|agg_ds] @ Wcat + b), fp16 inputs / fp32 accumulate.
// 128x96 block tile, 8 warps (4 m-groups x 2 n-groups), warp = 32x48.
// A staged [128][40] half (80B stride: conflict-free ldmatrix), B [32][104].
__global__ __launch_bounds__(256)
void gemm_layer_mma(const float* __restrict__ x0, int which_in, int layer,
                    int which_out, int n, const int* __restrict__ batch,
                    int do_pool)
{
    __shared__ __align__(16) __half As[128 * 40];
    __shared__ __align__(16) __half Bs[32 * 104];
    const float* xin = pick_in(x0, which_in);
    const __half* W16 = d_Wcat16 + layer * KC * HD;
    const float* bc = d_bcat + layer * HD;

    int bm   = blockIdx.x * 128;
    int tid  = threadIdx.x;
    int lane = tid & 31;
    int w    = tid >> 5;
    int mg   = (w >> 1) * 32;      // warp m offset within tile
    int ng   = (w & 1) * 48;       // warp n offset within tile

    uint32_t as_base = (uint32_t)__cvta_generic_to_shared(As);
    uint32_t bs_base = (uint32_t)__cvta_generic_to_shared(Bs);

    float acc[2][6][4];
#pragma unroll
    for (int mb = 0; mb < 2; ++mb)
#pragma unroll
        for (int nb = 0; nb < 6; ++nb)
#pragma unroll
            for (int q = 0; q < 4; ++q) acc[mb][nb][q] = 0.f;

    half2* As2 = reinterpret_cast<half2*>(As);
    half2* Bs2 = reinterpret_cast<half2*>(Bs);

#pragma unroll 1
    for (int kc = 0; kc < 9; ++kc) {
        const float* src = (kc < 3) ? xin : (kc < 6 ? d_agg_sd : d_agg_ds);
        const float2* src2 = reinterpret_cast<const float2*>(src);
        int kl2 = (kc % 3) * 16;   // float2 offset within row
        // ---- stage A: 128 rows x 32 k (fp32 -> fp16 in registers) ----
#pragma unroll
        for (int it = 0; it < 8; ++it) {
            int i = it * 256 + tid;
            int m = i >> 4, c = i & 15;
            int gm = bm + m;
            half2 h = __floats2half2_rn(0.f, 0.f);
            if (gm < n) {
                float2 v = src2[(size_t)gm * 48 + kl2 + c];
                h = __floats2half2_rn(v.x, v.y);
            }
            As2[m * 20 + c] = h;
        }
        // ---- stage B: 32 k x 96 n (fp16 weights) ----
        const half2* Wk2 = reinterpret_cast<const half2*>(W16 + kc * 32 * HD);
#pragma unroll
        for (int it = 0; it < 6; ++it) {
            int i = it * 256 + tid;
            int k = i / 48, c = i % 48;
            Bs2[k * 52 + c] = Wk2[k * 48 + c];
        }
        __syncthreads();
        // ---- 2 x k16 MMA steps ----
#pragma unroll
        for (int ks = 0; ks < 32; ks += 16) {
            uint32_t a[2][4], b[6][2];
#pragma unroll
            for (int mb = 0; mb < 2; ++mb) {
                uint32_t addr = as_base +
                    2u * ((mg + mb * 16 + (lane & 15)) * 40 + ks + (lane >> 4) * 8);
                ldsm_x4(a[mb], addr);
            }
#pragma unroll
            for (int nb = 0; nb < 6; ++nb) {
                uint32_t addr = bs_base +
                    2u * ((ks + (lane & 15)) * 104 + ng + nb * 8);
                ldsm_x2t(b[nb], addr);
            }
#pragma unroll
            for (int mb = 0; mb < 2; ++mb)
#pragma unroll
                for (int nb = 0; nb < 6; ++nb)
                    mma16816(acc[mb][nb], a[mb], b[nb]);
        }
        __syncthreads();
    }

    // ---- epilogue: bias + relu (+ fused max-pool on last layer) ----
    int r  = lane >> 2;
    int cp = (lane & 3) * 2;
    if (!do_pool) {
        float* out = pick_buf(which_out);
#pragma unroll
        for (int mb = 0; mb < 2; ++mb) {
            int gm0 = bm + mg + mb * 16 + r;
#pragma unroll
            for (int nb = 0; nb < 6; ++nb) {
                int j = ng + nb * 8 + cp;
                float2 bv = *reinterpret_cast<const float2*>(&bc[j]);
                if (gm0 < n) {
                    float2 o = make_float2(fmaxf(acc[mb][nb][0] + bv.x, 0.f),
                                           fmaxf(acc[mb][nb][1] + bv.y, 0.f));
                    *reinterpret_cast<float2*>(&out[(size_t)gm0 * HD + j]) = o;
                }
                int gm1 = gm0 + 8;
                if (gm1 < n) {
                    float2 o = make_float2(fmaxf(acc[mb][nb][2] + bv.x, 0.f),
                                           fmaxf(acc[mb][nb][3] + bv.y, 0.f));
                    *reinterpret_cast<float2*>(&out[(size_t)gm1 * HD + j]) = o;
                }
            }
        }
    } else {
#pragma unroll
        for (int mb = 0; mb < 2; ++mb) {
            int gm0 = bm + mg + mb * 16 + r;
#pragma unroll
            for (int nb = 0; nb < 6; ++nb) {
                int j = ng + nb * 8 + cp;
                float2 bv = *reinterpret_cast<const float2*>(&bc[j]);
                if (gm0 < n) {
                    int g = batch[gm0];
                    float v0 = fmaxf(acc[mb][nb][0] + bv.x, 0.f);
                    float v1 = fmaxf(acc[mb][nb][1] + bv.y, 0.f);
                    atomicMax((int*)&d_gpool[g * HD + j],     __float_as_int(v0));
                    atomicMax((int*)&d_gpool[g * HD + j + 1], __float_as_int(v1));
                }
                int gm1 = gm0 + 8;
                if (gm1 < n) {
                    int g = batch[gm1];
                    float v2 = fmaxf(acc[mb][nb][2] + bv.x, 0.f);
                    float v3 = fmaxf(acc[mb][nb][3] + bv.y, 0.f);
                    atomicMax((int*)&d_gpool[g * HD + j],     __float_as_int(v2));
                    atomicMax((int*)&d_gpool[g * HD + j + 1], __float_as_int(v3));
                }
            }
        }
    }
}

// ---------------- final MLP --------------------------------------------------
__global__ void mlp_head(const float* __restrict__ w1, const float* __restrict__ b1,
                         const float* __restrict__ w2, const float* __restrict__ b2,
                         float* __restrict__ out, int g)
{
    int t = blockIdx.x * blockDim.x + threadIdx.x;
    if (t >= g) return;
    float o = b2[0];
#pragma unroll
    for (int j = 0; j < 5; ++j) {
        float s = b1[j];
        for (int k = 0; k < HD; ++k)
            s += d_gpool[t * HD + k] * w1[k * 5 + j];
        o += fmaxf(s, 0.f) * w2[j];
    }
    out[t] = o;
}

// ---------------- launch -----------------------------------------------------
extern "C" void kernel_launch(void* const* d_in, const int* in_sizes, int n_in,
                              void* d_out, int out_size)
{
    const float* x     = (const float*)d_in[0];
    const int*   ei    = (const int*)d_in[1];
    const int*   batch = (const int*)d_in[2];
    int n = in_sizes[0] / HD;
    int e = in_sizes[1] / 2;
    if (n > NMAX) n = NMAX;
    if (e > EMAX) e = EMAX;
    int g = out_size;
    if (g > GMAX) g = GMAX;

    bool sig = (in_sizes[4] == HD);
    auto Wp = [&](int l, int t) -> const float* {
        int base = 3 + l * 6;
        return (const float*)d_in[base + (sig ? t * 2 : t)];
    };
    auto bp = [&](int l, int t) -> const float* {
        int base = 3 + l * 6;
        return (const float*)d_in[base + (sig ? t * 2 + 1 : 3 + t)];
    };
    const float* lin1_w = (const float*)d_in[21];
    const float* lin1_b = (const float*)d_in[22];
    const float* lin2_w = (const float*)d_in[23];
    const float* lin2_b = (const float*)d_in[24];

    prep_all<<<(3 * KC * HD + 255) / 256, 256>>>(
        Wp(0,0), Wp(0,1), Wp(0,2), bp(0,0), bp(0,1), bp(0,2),
        Wp(1,0), Wp(1,1), Wp(1,2), bp(1,0), bp(1,1), bp(1,2),
        Wp(2,0), Wp(2,1), Wp(2,2), bp(2,0), bp(2,1), bp(2,2), n);

    int nb = (n + SCAN_B - 1) / SCAN_B;
    count_deg<<<(e + 255) / 256, 256>>>(ei, e);
    deg_block_sums<<<nb, SCAN_B>>>(n);
    scan_block_sums<<<1, NBLK_MAX>>>(nb);
    write_offsets<<<nb, SCAN_B>>>(n);
    fill_csr<<<(e + 255) / 256, 256>>>(ei, e);

    const int in_sel[3]  = {0, 1, 2};  // x, hA, hB
    const int out_sel[3] = {1, 2, 1};  // hA, hB, (pooled; buffer unused)
    for (int l = 0; l < 3; ++l) {
        gather_agg<<<(2 * n + 7) / 8, 256>>>(x, in_sel[l], n);
        gemm_layer_mma<<<(n + 127) / 128, 256>>>(x, in_sel[l], l, out_sel[l], n,
                                                 batch, l == 2 ? 1 : 0);
    }

    mlp_head<<<1, 128>>>(lin1_w, lin1_b, lin2_w, lin2_b, (float*)d_out, g);
}

// round 17
// speedup vs baseline: 2.2216x; 1.0013x over previous
#include <cuda_runtime.h>
#include <cuda_fp16.h>
#include <cstdint>

#define NMAX 50000
#define EMAX 800000
#define HD   96          // hidden/feature dim
#define KC   288         // 3*HD concatenated K dim
#define GMAX 64
#define ALPHA 0.5f
#define SCAN_B 256
#define NBLK_MAX 256     // ceil(NMAX/SCAN_B) = 196 <= 256

// ---------------- static device scratch (no runtime allocation) -------------
__device__ __align__(16) float  d_hA[NMAX * HD];
__device__ __align__(16) float  d_hB[NMAX * HD];
__device__ __align__(16) float  d_agg_sd[NMAX * HD];
__device__ __align__(16) float  d_agg_ds[NMAX * HD];
__device__ int    d_deg_dst[NMAX];
__device__ int    d_deg_src[NMAX];
__device__ int    d_cnt_in[NMAX];
__device__ int    d_cnt_out[NMAX];
__device__ int    d_off_in[NMAX + 1];
__device__ int    d_off_out[NMAX + 1];
__device__ int    d_blk_in[NBLK_MAX];
__device__ int    d_blk_out[NBLK_MAX];
__device__ int    d_in_nbr[EMAX];
__device__ int    d_out_nbr[EMAX];
__device__ float  d_inv_dd[NMAX];
__device__ float  d_inv_ds[NMAX];
__device__ float  d_Wcat[3 * KC * HD];
__device__ __align__(16) __half d_Wcat16[3 * KC * HD];
__device__ float  d_bcat[3 * HD];
__device__ float  d_gpool[GMAX * HD];

__device__ __forceinline__ const float* pick_in(const float* x0, int which) {
    return which == 0 ? x0 : (which == 1 ? d_hA : d_hB);
}
__device__ __forceinline__ float* pick_buf(int which) {
    return which == 1 ? d_hA : d_hB;
}

// ---------------- fused prolog: weights (fp32+fp16) + zeroing ---------------
__global__ void prep_all(
    const float* W0s, const float* W0sd, const float* W0ds,
    const float* b0s, const float* b0sd, const float* b0ds,
    const float* W1s, const float* W1sd, const float* W1ds,
    const float* b1s, const float* b1sd, const float* b1ds,
    const float* W2s, const float* W2sd, const float* W2ds,
    const float* b2s, const float* b2sd, const float* b2ds, int n)
{
    int idx = blockIdx.x * blockDim.x + threadIdx.x;
    const float* Wtab[9] = {W0s, W0sd, W0ds, W1s, W1sd, W1ds, W2s, W2sd, W2ds};
    const float* btab[9] = {b0s, b0sd, b0ds, b1s, b1sd, b1ds, b2s, b2sd, b2ds};
    if (idx < 3 * KC * HD) {
        int l   = idx / (KC * HD);
        int rem = idx % (KC * HD);
        int r   = rem / HD, c = rem % HD;
        int region = r / HD, rr = r % HD;
        float scale = (region == 0) ? 1.f : (region == 1 ? (1.f - ALPHA) : ALPHA);
        float v = Wtab[l * 3 + region][rr * HD + c] * scale;
        d_Wcat[idx]   = v;
        d_Wcat16[idx] = __float2half_rn(v);
    }
    if (idx < 3 * HD) {
        int l = idx / HD, c = idx % HD;
        d_bcat[idx] = btab[l * 3 + 0][c]
                    + (1.f - ALPHA) * btab[l * 3 + 1][c]
                    + ALPHA * btab[l * 3 + 2][c];
    }
    if (idx < n) {
        d_deg_dst[idx] = 0; d_deg_src[idx] = 0;
        d_cnt_in[idx]  = 0; d_cnt_out[idx] = 0;
    }
    if (idx < GMAX * HD) d_gpool[idx] = 0.f;
}

// ---------------- degree / CSR build ----------------------------------------
__global__ void count_deg(const int* __restrict__ ei, int e) {
    int i = blockIdx.x * blockDim.x + threadIdx.x;
    if (i < e) {
        atomicAdd(&d_deg_src[ei[i]], 1);
        atomicAdd(&d_deg_dst[ei[e + i]], 1);
    }
}

__global__ void deg_block_sums(int n) {
    __shared__ int sa[SCAN_B], sb[SCAN_B];
    int t = threadIdx.x;
    int i = blockIdx.x * SCAN_B + t;
    sa[t] = (i < n) ? d_deg_dst[i] : 0;
    sb[t] = (i < n) ? d_deg_src[i] : 0;
    __syncthreads();
    for (int off = SCAN_B / 2; off > 0; off >>= 1) {
        if (t < off) { sa[t] += sa[t + off]; sb[t] += sb[t + off]; }
        __syncthreads();
    }
    if (t == 0) { d_blk_in[blockIdx.x] = sa[0]; d_blk_out[blockIdx.x] = sb[0]; }
}

__global__ void scan_block_sums(int nb) {
    __shared__ int sa[NBLK_MAX], sb[NBLK_MAX];
    int t = threadIdx.x;
    int va0 = (t < nb) ? d_blk_in[t] : 0;
    int vb0 = (t < nb) ? d_blk_out[t] : 0;
    sa[t] = va0; sb[t] = vb0;
    __syncthreads();
    for (int off = 1; off < NBLK_MAX; off <<= 1) {
        int va = (t >= off) ? sa[t - off] : 0;
        int vb = (t >= off) ? sb[t - off] : 0;
        __syncthreads();
        sa[t] += va; sb[t] += vb;
        __syncthreads();
    }
    if (t < nb) { d_blk_in[t] = sa[t] - va0; d_blk_out[t] = sb[t] - vb0; }
}

__global__ void write_offsets(int n) {
    __shared__ int sa[SCAN_B], sb[SCAN_B];
    int t = threadIdx.x;
    int i = blockIdx.x * SCAN_B + t;
    int da = (i < n) ? d_deg_dst[i] : 0;
    int db = (i < n) ? d_deg_src[i] : 0;
    sa[t] = da; sb[t] = db;
    __syncthreads();
    for (int off = 1; off < SCAN_B; off <<= 1) {
        int va = (t >= off) ? sa[t - off] : 0;
        int vb = (t >= off) ? sb[t - off] : 0;
        __syncthreads();
        sa[t] += va; sb[t] += vb;
        __syncthreads();
    }
    int pa = d_blk_in[blockIdx.x];
    int pb = d_blk_out[blockIdx.x];
    if (i < n) {
        d_off_in[i]  = pa + sa[t] - da;
        d_off_out[i] = pb + sb[t] - db;
        d_inv_dd[i] = 1.f / (float)max(da, 1);
        d_inv_ds[i] = 1.f / (float)max(db, 1);
        if (i == n - 1) {
            d_off_in[n]  = pa + sa[t];
            d_off_out[n] = pb + sb[t];
        }
    }
}

__global__ void fill_csr(const int* __restrict__ ei, int e) {
    int i = blockIdx.x * blockDim.x + threadIdx.x;
    if (i >= e) return;
    int s = ei[i], d = ei[e + i];
    int p = d_off_in[d]  + atomicAdd(&d_cnt_in[d], 1);
    d_in_nbr[p] = s;
    int q = d_off_out[s] + atomicAdd(&d_cnt_out[s], 1);
    d_out_nbr[q] = d;
}

// ---------------- gather: warp per (node, direction), ILP-4 (R9 champion) ---
__global__ __launch_bounds__(256)
void gather_agg(const float* __restrict__ x0, int which_in, int n)
{
    int task = blockIdx.x * 8 + (threadIdx.x >> 5);
    int lane = threadIdx.x & 31;
    int v = task >> 1, dir = task & 1;
    if (v >= n) return;
    const float* xin = pick_in(x0, which_in);

    const int* off = dir ? d_off_out : d_off_in;
    const int* nbr = dir ? d_out_nbr : d_in_nbr;
    float inv = dir ? d_inv_ds[v] : d_inv_dd[v];
    float* o = (dir ? d_agg_ds : d_agg_sd) + (size_t)v * HD;

    int k = off[v], end = off[v + 1];
    float a0 = 0.f, a1 = 0.f, a2 = 0.f;
    for (; k + 4 <= end; k += 4) {
        int u0 = __ldg(nbr + k);
        int u1 = __ldg(nbr + k + 1);
        int u2 = __ldg(nbr + k + 2);
        int u3 = __ldg(nbr + k + 3);
        const float* r0 = xin + (size_t)u0 * HD;
        const float* r1 = xin + (size_t)u1 * HD;
        const float* r2 = xin + (size_t)u2 * HD;
        const float* r3 = xin + (size_t)u3 * HD;
        float f00 = r0[lane], f01 = r0[lane + 32], f02 = r0[lane + 64];
        float f10 = r1[lane], f11 = r1[lane + 32], f12 = r1[lane + 64];
        float f20 = r2[lane], f21 = r2[lane + 32], f22 = r2[lane + 64];
        float f30 = r3[lane], f31 = r3[lane + 32], f32 = r3[lane + 64];
        a0 += (f00 + f10) + (f20 + f30);
        a1 += (f01 + f11) + (f21 + f31);
        a2 += (f02 + f12) + (f22 + f32);
    }
    for (; k < end; ++k) {
        int u = __ldg(nbr + k);
        const float* r = xin + (size_t)u * HD;
        a0 += r[lane]; a1 += r[lane + 32]; a2 += r[lane + 64];
    }
    o[lane] = a0 * inv; o[lane + 32] = a1 * inv; o[lane + 64] = a2 * inv;
}

// ---------------- tensor-core helpers ----------------------------------------
__device__ __forceinline__ void ldsm_x4(uint32_t* r, uint32_t addr) {
    asm volatile("ldmatrix.sync.aligned.m8n8.x4.shared.b16 {%0,%1,%2,%3}, [%4];"
                 : "=r"(r[0]), "=r"(r[1]), "=r"(r[2]), "=r"(r[3]) : "r"(addr));
}
__device__ __forceinline__ void ldsm_x2t(uint32_t* r, uint32_t addr) {
    asm volatile("ldmatrix.sync.aligned.m8n8.x2.trans.shared.b16 {%0,%1}, [%2];"
                 : "=r"(r[0]), "=r"(r[1]) : "r"(addr));
}
__device__ __forceinline__ void mma16816(float* d, const uint32_t* a, const uint32_t* b) {
    asm volatile("mma.sync.aligned.m16n8k16.row.col.f32.f16.f16.f32 "
                 "{%0,%1,%2,%3}, {%4,%5,%6,%7}, {%8,%9}, {%0,%1,%2,%3};"
                 : "+f"(d[0]), "+f"(d[1]), "+f"(d[2]), "+f"(d[3])
                 : "r"(a[0]), "r"(a[1]), "r"(a[2]), "r"(a[3]),
                   "r"(b[0]), "r"(b[1]));
}

// ---------------- fused layer GEMM on tensor cores ---------------------------
// out = relu([x|agg_sd|agg_ds] @ Wcat + b), fp16 inputs / fp32 accumulate.
// 128x96 block tile, 8 warps (4 m-groups x 2 n-groups), warp = 32x48.
// A staged [128][40] half (80B stride: conflict-free ldmatrix), B [32][104].
__global__ __launch_bounds__(256)
void gemm_layer_mma(const float* __restrict__ x0, int which_in, int layer,
                    int which_out, int n, const int* __restrict__ batch,
                    int do_pool)
{
    __shared__ __align__(16) __half As[128 * 40];
    __shared__ __align__(16) __half Bs[32 * 104];
    const float* xin = pick_in(x0, which_in);
    const __half* W16 = d_Wcat16 + layer * KC * HD;
    const float* bc = d_bcat + layer * HD;

    int bm   = blockIdx.x * 128;
    int tid  = threadIdx.x;
    int lane = tid & 31;
    int w    = tid >> 5;
    int mg   = (w >> 1) * 32;      // warp m offset within tile
    int ng   = (w & 1) * 48;       // warp n offset within tile

    uint32_t as_base = (uint32_t)__cvta_generic_to_shared(As);
    uint32_t bs_base = (uint32_t)__cvta_generic_to_shared(Bs);

    float acc[2][6][4];
#pragma unroll
    for (int mb = 0; mb < 2; ++mb)
#pragma unroll
        for (int nb = 0; nb < 6; ++nb)
#pragma unroll
            for (int q = 0; q < 4; ++q) acc[mb][nb][q] = 0.f;

    half2* As2 = reinterpret_cast<half2*>(As);
    half2* Bs2 = reinterpret_cast<half2*>(Bs);

#pragma unroll 1
    for (int kc = 0; kc < 9; ++kc) {
        const float* src = (kc < 3) ? xin : (kc < 6 ? d_agg_sd : d_agg_ds);
        const float2* src2 = reinterpret_cast<const float2*>(src);
        int kl2 = (kc % 3) * 16;   // float2 offset within row
        // ---- stage A: 128 rows x 32 k (fp32 -> fp16 in registers) ----
#pragma unroll
        for (int it = 0; it < 8; ++it) {
            int i = it * 256 + tid;
            int m = i >> 4, c = i & 15;
            int gm = bm + m;
            half2 h = __floats2half2_rn(0.f, 0.f);
            if (gm < n) {
                float2 v = src2[(size_t)gm * 48 + kl2 + c];
                h = __floats2half2_rn(v.x, v.y);
            }
            As2[m * 20 + c] = h;
        }
        // ---- stage B: 32 k x 96 n (fp16 weights) ----
        const half2* Wk2 = reinterpret_cast<const half2*>(W16 + kc * 32 * HD);
#pragma unroll
        for (int it = 0; it < 6; ++it) {
            int i = it * 256 + tid;
            int k = i / 48, c = i % 48;
            Bs2[k * 52 + c] = Wk2[k * 48 + c];
        }
        __syncthreads();
        // ---- 2 x k16 MMA steps ----
#pragma unroll
        for (int ks = 0; ks < 32; ks += 16) {
            uint32_t a[2][4], b[6][2];
#pragma unroll
            for (int mb = 0; mb < 2; ++mb) {
                uint32_t addr = as_base +
                    2u * ((mg + mb * 16 + (lane & 15)) * 40 + ks + (lane >> 4) * 8);
                ldsm_x4(a[mb], addr);
            }
#pragma unroll
            for (int nb = 0; nb < 6; ++nb) {
                uint32_t addr = bs_base +
                    2u * ((ks + (lane & 15)) * 104 + ng + nb * 8);
                ldsm_x2t(b[nb], addr);
            }
#pragma unroll
            for (int mb = 0; mb < 2; ++mb)
#pragma unroll
                for (int nb = 0; nb < 6; ++nb)
                    mma16816(acc[mb][nb], a[mb], b[nb]);
        }
        __syncthreads();
    }

    // ---- epilogue: bias + relu (+ fused max-pool on last layer) ----
    int r  = lane >> 2;
    int cp = (lane & 3) * 2;
    if (!do_pool) {
        float* out = pick_buf(which_out);
#pragma unroll
        for (int mb = 0; mb < 2; ++mb) {
            int gm0 = bm + mg + mb * 16 + r;
#pragma unroll
            for (int nb = 0; nb < 6; ++nb) {
                int j = ng + nb * 8 + cp;
                float2 bv = *reinterpret_cast<const float2*>(&bc[j]);
                if (gm0 < n) {
                    float2 o = make_float2(fmaxf(acc[mb][nb][0] + bv.x, 0.f),
                                           fmaxf(acc[mb][nb][1] + bv.y, 0.f));
                    *reinterpret_cast<float2*>(&out[(size_t)gm0 * HD + j]) = o;
                }
                int gm1 = gm0 + 8;
                if (gm1 < n) {
                    float2 o = make_float2(fmaxf(acc[mb][nb][2] + bv.x, 0.f),
                                           fmaxf(acc[mb][nb][3] + bv.y, 0.f));
                    *reinterpret_cast<float2*>(&out[(size_t)gm1 * HD + j]) = o;
                }
            }
        }
    } else {
#pragma unroll
        for (int mb = 0; mb < 2; ++mb) {
            int gm0 = bm + mg + mb * 16 + r;
#pragma unroll
            for (int nb = 0; nb < 6; ++nb) {
                int j = ng + nb * 8 + cp;
                float2 bv = *reinterpret_cast<const float2*>(&bc[j]);
                if (gm0 < n) {
                    int g = batch[gm0];
                    float v0 = fmaxf(acc[mb][nb][0] + bv.x, 0.f);
                    float v1 = fmaxf(acc[mb][nb][1] + bv.y, 0.f);
                    atomicMax((int*)&d_gpool[g * HD + j],     __float_as_int(v0));
                    atomicMax((int*)&d_gpool[g * HD + j + 1], __float_as_int(v1));
                }
                int gm1 = gm0 + 8;
                if (gm1 < n) {
                    int g = batch[gm1];
                    float v2 = fmaxf(acc[mb][nb][2] + bv.x, 0.f);
                    float v3 = fmaxf(acc[mb][nb][3] + bv.y, 0.f);
                    atomicMax((int*)&d_gpool[g * HD + j],     __float_as_int(v2));
                    atomicMax((int*)&d_gpool[g * HD + j + 1], __float_as_int(v3));
                }
            }
        }
    }
}

// ---------------- final MLP --------------------------------------------------
__global__ void mlp_head(const float* __restrict__ w1, const float* __restrict__ b1,
                         const float* __restrict__ w2, const float* __restrict__ b2,
                         float* __restrict__ out, int g)
{
    int t = blockIdx.x * blockDim.x + threadIdx.x;
    if (t >= g) return;
    float o = b2[0];
#pragma unroll
    for (int j = 0; j < 5; ++j) {
        float s = b1[j];
        for (int k = 0; k < HD; ++k)
            s += d_gpool[t * HD + k] * w1[k * 5 + j];
        o += fmaxf(s, 0.f) * w2[j];
    }
    out[t] = o;
}

// ---------------- launch -----------------------------------------------------
extern "C" void kernel_launch(void* const* d_in, const int* in_sizes, int n_in,
                              void* d_out, int out_size)
{
    const float* x     = (const float*)d_in[0];
    const int*   ei    = (const int*)d_in[1];
    const int*   batch = (const int*)d_in[2];
    int n = in_sizes[0] / HD;
    int e = in_sizes[1] / 2;
    if (n > NMAX) n = NMAX;
    if (e > EMAX) e = EMAX;
    int g = out_size;
    if (g > GMAX) g = GMAX;

    bool sig = (in_sizes[4] == HD);
    auto Wp = [&](int l, int t) -> const float* {
        int base = 3 + l * 6;
        return (const float*)d_in[base + (sig ? t * 2 : t)];
    };
    auto bp = [&](int l, int t) -> const float* {
        int base = 3 + l * 6;
        return (const float*)d_in[base + (sig ? t * 2 + 1 : 3 + t)];
    };
    const float* lin1_w = (const float*)d_in[21];
    const float* lin1_b = (const float*)d_in[22];
    const float* lin2_w = (const float*)d_in[23];
    const float* lin2_b = (const float*)d_in[24];

    prep_all<<<(3 * KC * HD + 255) / 256, 256>>>(
        Wp(0,0), Wp(0,1), Wp(0,2), bp(0,0), bp(0,1), bp(0,2),
        Wp(1,0), Wp(1,1), Wp(1,2), bp(1,0), bp(1,1), bp(1,2),
        Wp(2,0), Wp(2,1), Wp(2,2), bp(2,0), bp(2,1), bp(2,2), n);

    int nb = (n + SCAN_B - 1) / SCAN_B;
    count_deg<<<(e + 255) / 256, 256>>>(ei, e);
    deg_block_sums<<<nb, SCAN_B>>>(n);
    scan_block_sums<<<1, NBLK_MAX>>>(nb);
    write_offsets<<<nb, SCAN_B>>>(n);
    fill_csr<<<(e + 255) / 256, 256>>>(ei, e);

    const int in_sel[3]  = {0, 1, 2};  // x, hA, hB
    const int out_sel[3] = {1, 2, 1};  // hA, hB, (pooled; buffer unused)
    for (int l = 0; l < 3; ++l) {
        gather_agg<<<(2 * n + 7) / 8, 256>>>(x, in_sel[l], n);
        gemm_layer_mma<<<(n + 127) / 128, 256>>>(x, in_sel[l], l, out_sel[l], n,
                                                 batch, l == 2 ? 1 : 0);
    }

    mlp_head<<<1, 128>>>(lin1_w, lin1_b, lin2_w, lin2_b, (float*)d_out, g);
}